// round 4
// baseline (speedup 1.0000x reference)
#include <cuda_runtime.h>
#include <cuda_bf16.h>
#include <cstdint>

#define N_NODES 50000
#define N_EDGES 800000
#define D_IN    256
#define D_OUT   256

#define N_CHUNKS   4
#define CHUNK_COLS 64     // D_OUT / N_CHUNKS

// ---------------- static device scratch (no allocations) -------------------
__device__ float g_xw[(size_t)N_NODES * D_OUT];   // 51.2 MB
__device__ int   g_deg[N_NODES];
__device__ int   g_fill[N_NODES];
__device__ int   g_rowptr[N_NODES + 1];
__device__ int2  g_epack[N_EDGES];                // {col, bitcast(val)}

// ---------------------------------------------------------------------------
// GEMM chunk: xw[:, c0:c0+64] = x @ W[:, c0:c0+64]
// 128x64 tile, BK=8, 256 threads, 8x4 microtile.
// ---------------------------------------------------------------------------
#define GBM 128
#define GBN 64
#define GBK 8

__global__ __launch_bounds__(256)
void gemm_chunk_kernel(const float* __restrict__ x,
                       const float* __restrict__ W,
                       int col0)
{
    __shared__ float As[GBK][GBM];
    __shared__ float Bs[GBK][GBN];

    const int t    = threadIdx.x;
    const int row0 = blockIdx.x * GBM;

    const int a_m = t >> 1;          // 0..127
    const int a_k = (t & 1) * 4;     // 0,4
    const int b_k = t >> 5;          // 0..7
    const int b_n = (t & 31) * 2;    // 0..62

    const int tx = t & 15;           // col group: tx*4
    const int ty = t >> 4;           // row groups: ty*4, ty*4+64

    float acc[8][4];
    #pragma unroll
    for (int i = 0; i < 8; i++)
        #pragma unroll
        for (int j = 0; j < 4; j++) acc[i][j] = 0.f;

    for (int k0 = 0; k0 < D_IN; k0 += GBK) {
        float4 av = make_float4(0.f, 0.f, 0.f, 0.f);
        const int gm = row0 + a_m;
        if (gm < N_NODES)
            av = *reinterpret_cast<const float4*>(&x[(size_t)gm * D_IN + k0 + a_k]);
        As[a_k + 0][a_m] = av.x;
        As[a_k + 1][a_m] = av.y;
        As[a_k + 2][a_m] = av.z;
        As[a_k + 3][a_m] = av.w;

        const float2 bv = *reinterpret_cast<const float2*>(
            &W[(size_t)(k0 + b_k) * D_OUT + col0 + b_n]);
        Bs[b_k][b_n]     = bv.x;
        Bs[b_k][b_n + 1] = bv.y;

        __syncthreads();

        #pragma unroll
        for (int k = 0; k < GBK; k++) {
            float a[8], b[4];
            *reinterpret_cast<float4*>(&a[0]) = *reinterpret_cast<const float4*>(&As[k][ty * 4]);
            *reinterpret_cast<float4*>(&a[4]) = *reinterpret_cast<const float4*>(&As[k][ty * 4 + 64]);
            *reinterpret_cast<float4*>(&b[0]) = *reinterpret_cast<const float4*>(&Bs[k][tx * 4]);
            #pragma unroll
            for (int i = 0; i < 8; i++)
                #pragma unroll
                for (int j = 0; j < 4; j++)
                    acc[i][j] = fmaf(a[i], b[j], acc[i][j]);
        }
        __syncthreads();
    }

    #pragma unroll
    for (int i = 0; i < 8; i++) {
        const int gm = row0 + ty * 4 + ((i < 4) ? i : (64 + i - 4));
        if (gm < N_NODES) {
            *reinterpret_cast<float4*>(&g_xw[(size_t)gm * D_OUT + col0 + tx * 4]) =
                make_float4(acc[i][0], acc[i][1], acc[i][2], acc[i][3]);
        }
    }
}

// ---------------------------------------------------------------------------
// CSR construction
// ---------------------------------------------------------------------------
__global__ __launch_bounds__(256)
void zero_counts_kernel()
{
    int i = blockIdx.x * blockDim.x + threadIdx.x;
    if (i < N_NODES) { g_deg[i] = 0; g_fill[i] = 0; }
}

__global__ __launch_bounds__(256)
void count_kernel(const int* __restrict__ edge_row)
{
    int e = blockIdx.x * blockDim.x + threadIdx.x;
    if (e < N_EDGES) atomicAdd(&g_deg[edge_row[e]], 1);
}

__global__ __launch_bounds__(1024)
void scan_kernel()
{
    __shared__ int partial[1024];
    const int t = threadIdx.x;
    const int CHUNK = (N_NODES + 1023) / 1024;
    const int base = t * CHUNK;

    int s = 0;
    for (int i = 0; i < CHUNK; i++) {
        int idx = base + i;
        if (idx < N_NODES) s += g_deg[idx];
    }
    partial[t] = s;
    __syncthreads();

    for (int off = 1; off < 1024; off <<= 1) {
        int v = (t >= off) ? partial[t - off] : 0;
        __syncthreads();
        partial[t] += v;
        __syncthreads();
    }

    int run = (t == 0) ? 0 : partial[t - 1];
    for (int i = 0; i < CHUNK; i++) {
        int idx = base + i;
        if (idx < N_NODES) { g_rowptr[idx] = run; run += g_deg[idx]; }
    }
    if (t == 1023) g_rowptr[N_NODES] = partial[1023];
}

__global__ __launch_bounds__(256)
void fill_kernel(const int*   __restrict__ edge_row,
                 const int*   __restrict__ edge_col,
                 const float* __restrict__ edge_vals)
{
    int e = blockIdx.x * blockDim.x + threadIdx.x;
    if (e >= N_EDGES) return;
    const int r = edge_row[e];
    const int p = g_rowptr[r] + atomicAdd(&g_fill[r], 1);
    g_epack[p] = make_int2(edge_col[e], __float_as_int(edge_vals[e]));
}

// ---------------------------------------------------------------------------
// SpMM chunk: out[:, co:co+64] = relu(A @ xw[:, co:co+64] + bias[co:co+64])
// One warp per row; lane owns float2; 8-edge unroll for MLP.
// ---------------------------------------------------------------------------
__global__ __launch_bounds__(256)
void spmm_chunk_kernel(const float* __restrict__ bias,
                       float*       __restrict__ out,
                       int co)
{
    const int warp = (blockIdx.x * blockDim.x + threadIdx.x) >> 5;
    const int lane = threadIdx.x & 31;
    if (warp >= N_NODES) return;

    const int s = g_rowptr[warp];
    const int e = g_rowptr[warp + 1];
    const int c = co + lane * 2;

    float2 acc = make_float2(0.f, 0.f);

    int i = s;
    for (; i + 7 < e; i += 8) {
        int2   p[8];
        float2 m[8];
        #pragma unroll
        for (int j = 0; j < 8; j++) p[j] = __ldg(&g_epack[i + j]);
        #pragma unroll
        for (int j = 0; j < 8; j++)
            m[j] = __ldg(reinterpret_cast<const float2*>(&g_xw[(size_t)p[j].x * D_OUT + c]));
        #pragma unroll
        for (int j = 0; j < 8; j++) {
            const float v = __int_as_float(p[j].y);
            acc.x = fmaf(v, m[j].x, acc.x);
            acc.y = fmaf(v, m[j].y, acc.y);
        }
    }
    for (; i < e; i++) {
        const int2 p = __ldg(&g_epack[i]);
        const float v = __int_as_float(p.y);
        const float2 m = __ldg(reinterpret_cast<const float2*>(&g_xw[(size_t)p.x * D_OUT + c]));
        acc.x = fmaf(v, m.x, acc.x);
        acc.y = fmaf(v, m.y, acc.y);
    }

    const float2 b = *reinterpret_cast<const float2*>(&bias[c]);
    acc.x = fmaxf(acc.x + b.x, 0.f);
    acc.y = fmaxf(acc.y + b.y, 0.f);

    *reinterpret_cast<float2*>(&out[(size_t)warp * D_OUT + c]) = acc;
}

// ---------------------------------------------------------------------------
// Launch: software pipeline over D_OUT chunks.
//   side stream : GEMM chunk 0..3  (event after each)
//   main stream : CSR build, then SpMM chunk k after event k
// ---------------------------------------------------------------------------
static cudaStream_t g_side = nullptr;
static cudaEvent_t  g_fork = nullptr;
static cudaEvent_t  g_ev[N_CHUNKS] = {nullptr, nullptr, nullptr, nullptr};

extern "C" void kernel_launch(void* const* d_in, const int* in_sizes, int n_in,
                              void* d_out, int out_size)
{
    const float* x         = (const float*)d_in[0];
    const int*   edge_row  = (const int*)  d_in[1];
    const int*   edge_col  = (const int*)  d_in[2];
    const float* edge_vals = (const float*)d_in[3];
    const float* weight    = (const float*)d_in[4];
    const float* bias      = (const float*)d_in[5];
    float* out = (float*)d_out;

    if (g_side == nullptr) {
        cudaStreamCreateWithFlags(&g_side, cudaStreamNonBlocking);
        cudaEventCreateWithFlags(&g_fork, cudaEventDisableTiming);
        for (int k = 0; k < N_CHUNKS; k++)
            cudaEventCreateWithFlags(&g_ev[k], cudaEventDisableTiming);
    }

    // Fork side stream off the launch stream
    cudaEventRecord(g_fork, 0);
    cudaStreamWaitEvent(g_side, g_fork, 0);

    // Side stream: GEMM chunks
    const int gemm_blocks = (N_NODES + GBM - 1) / GBM;
    for (int k = 0; k < N_CHUNKS; k++) {
        gemm_chunk_kernel<<<gemm_blocks, 256, 0, g_side>>>(x, weight, k * CHUNK_COLS);
        cudaEventRecord(g_ev[k], g_side);
    }

    // Main stream: CSR build (overlaps GEMM chunk 0)
    zero_counts_kernel<<<(N_NODES + 255) / 256, 256>>>();
    count_kernel<<<(N_EDGES + 255) / 256, 256>>>(edge_row);
    scan_kernel<<<1, 1024>>>();
    fill_kernel<<<(N_EDGES + 255) / 256, 256>>>(edge_row, edge_col, edge_vals);

    // Main stream: SpMM chunks, each gated on its GEMM chunk
    const int spmm_blocks = (N_NODES * 32 + 255) / 256;
    for (int k = 0; k < N_CHUNKS; k++) {
        cudaStreamWaitEvent(0, g_ev[k], 0);
        spmm_chunk_kernel<<<spmm_blocks, 256>>>(bias, out, k * CHUNK_COLS);
    }
}

// round 5
// speedup vs baseline: 1.1599x; 1.1599x over previous
#include <cuda_runtime.h>
#include <cuda_bf16.h>
#include <cstdint>

#define N_NODES 50000
#define N_EDGES 800000
#define D_IN    256
#define D_OUT   256

#define N_CHUNKS   2
#define CHUNK_COLS 128

// ---------------- static device scratch (no allocations) -------------------
__device__ float g_xw[(size_t)N_NODES * D_OUT];   // 51.2 MB
__device__ int   g_deg[N_NODES];
__device__ int   g_fill[N_NODES];
__device__ int   g_rowptr[N_NODES + 1];
__device__ int2  g_epack[N_EDGES];                // {col, bitcast(val)}

// ---------------------------------------------------------------------------
// GEMM chunk: xw[:, col0:col0+128] = x @ W[:, col0:col0+128]
// 64x128 tile, BK=16, 256 threads, 8x4 microtile, double-buffered smem.
// ---------------------------------------------------------------------------
#define GBM 64
#define GBN 128
#define GBK 16
#define APAD 68   // 64 + 4 pad (keeps 16B alignment, breaks bank conflicts)

__global__ __launch_bounds__(256)
void gemm_chunk_kernel(const float* __restrict__ x,
                       const float* __restrict__ W,
                       int col0)
{
    __shared__ float As[2][GBK][APAD];
    __shared__ float Bs[2][GBK][GBN];

    const int t    = threadIdx.x;
    const int row0 = blockIdx.x * GBM;

    // A loads: 64 rows x 16 k = 256 float4, one per thread (transposed store)
    const int a_m = t >> 2;            // 0..63
    const int a_k = (t & 3) * 4;       // 0,4,8,12
    // B loads: 16 k x 128 n = 512 float4, two per thread (conflict-free)
    const int b_k = t >> 5;            // 0..7 (and +8)
    const int b_n = (t & 31) * 4;      // 0..124

    // Microtile: 8 rows x 4 cols
    const int ty = t >> 5;             // 0..7  -> rows ty*8 .. ty*8+7
    const int tx = t & 31;             // 0..31 -> cols tx*4

    const int gm_a   = row0 + a_m;
    const bool a_ok  = (gm_a < N_NODES);
    const float* a_ptr = x + (size_t)gm_a * D_IN + a_k;

    float acc[8][4];
    #pragma unroll
    for (int i = 0; i < 8; i++)
        #pragma unroll
        for (int j = 0; j < 4; j++) acc[i][j] = 0.f;

    // Preload step 0
    float4 ra = make_float4(0.f, 0.f, 0.f, 0.f);
    if (a_ok) ra = *reinterpret_cast<const float4*>(a_ptr);
    float4 rb0 = *reinterpret_cast<const float4*>(&W[(size_t)b_k * D_OUT + col0 + b_n]);
    float4 rb1 = *reinterpret_cast<const float4*>(&W[(size_t)(b_k + 8) * D_OUT + col0 + b_n]);

    As[0][a_k + 0][a_m] = ra.x;
    As[0][a_k + 1][a_m] = ra.y;
    As[0][a_k + 2][a_m] = ra.z;
    As[0][a_k + 3][a_m] = ra.w;
    *reinterpret_cast<float4*>(&Bs[0][b_k][b_n])     = rb0;
    *reinterpret_cast<float4*>(&Bs[0][b_k + 8][b_n]) = rb1;
    __syncthreads();

    int buf = 0;
    const int NSTEPS = D_IN / GBK;   // 16

    for (int s = 0; s < NSTEPS; s++) {
        float4 na, nb0, nb1;
        if (s < NSTEPS - 1) {
            const int kn = (s + 1) * GBK;
            na = make_float4(0.f, 0.f, 0.f, 0.f);
            if (a_ok) na = *reinterpret_cast<const float4*>(a_ptr + kn);
            nb0 = *reinterpret_cast<const float4*>(&W[(size_t)(kn + b_k) * D_OUT + col0 + b_n]);
            nb1 = *reinterpret_cast<const float4*>(&W[(size_t)(kn + b_k + 8) * D_OUT + col0 + b_n]);
        }

        #pragma unroll
        for (int k = 0; k < GBK; k++) {
            float a[8], b[4];
            *reinterpret_cast<float4*>(&a[0]) = *reinterpret_cast<const float4*>(&As[buf][k][ty * 8]);
            *reinterpret_cast<float4*>(&a[4]) = *reinterpret_cast<const float4*>(&As[buf][k][ty * 8 + 4]);
            *reinterpret_cast<float4*>(&b[0]) = *reinterpret_cast<const float4*>(&Bs[buf][k][tx * 4]);
            #pragma unroll
            for (int i = 0; i < 8; i++)
                #pragma unroll
                for (int j = 0; j < 4; j++)
                    acc[i][j] = fmaf(a[i], b[j], acc[i][j]);
        }

        if (s < NSTEPS - 1) {
            const int nb = buf ^ 1;
            As[nb][a_k + 0][a_m] = na.x;
            As[nb][a_k + 1][a_m] = na.y;
            As[nb][a_k + 2][a_m] = na.z;
            As[nb][a_k + 3][a_m] = na.w;
            *reinterpret_cast<float4*>(&Bs[nb][b_k][b_n])     = nb0;
            *reinterpret_cast<float4*>(&Bs[nb][b_k + 8][b_n]) = nb1;
            __syncthreads();
            buf = nb;
        }
    }

    #pragma unroll
    for (int i = 0; i < 8; i++) {
        const int gm = row0 + ty * 8 + i;
        if (gm < N_NODES) {
            *reinterpret_cast<float4*>(&g_xw[(size_t)gm * D_OUT + col0 + tx * 4]) =
                make_float4(acc[i][0], acc[i][1], acc[i][2], acc[i][3]);
        }
    }
}

// ---------------------------------------------------------------------------
// CSR construction
// ---------------------------------------------------------------------------
__global__ __launch_bounds__(256)
void zero_counts_kernel()
{
    int i = blockIdx.x * blockDim.x + threadIdx.x;
    if (i < N_NODES) { g_deg[i] = 0; g_fill[i] = 0; }
}

__global__ __launch_bounds__(256)
void count_kernel(const int* __restrict__ edge_row)
{
    int e = blockIdx.x * blockDim.x + threadIdx.x;
    if (e < N_EDGES) atomicAdd(&g_deg[edge_row[e]], 1);
}

__global__ __launch_bounds__(1024)
void scan_kernel()
{
    __shared__ int partial[1024];
    const int t = threadIdx.x;
    const int CHUNK = (N_NODES + 1023) / 1024;
    const int base = t * CHUNK;

    int s = 0;
    for (int i = 0; i < CHUNK; i++) {
        int idx = base + i;
        if (idx < N_NODES) s += g_deg[idx];
    }
    partial[t] = s;
    __syncthreads();

    for (int off = 1; off < 1024; off <<= 1) {
        int v = (t >= off) ? partial[t - off] : 0;
        __syncthreads();
        partial[t] += v;
        __syncthreads();
    }

    int run = (t == 0) ? 0 : partial[t - 1];
    for (int i = 0; i < CHUNK; i++) {
        int idx = base + i;
        if (idx < N_NODES) { g_rowptr[idx] = run; run += g_deg[idx]; }
    }
    if (t == 1023) g_rowptr[N_NODES] = partial[1023];
}

__global__ __launch_bounds__(256)
void fill_kernel(const int*   __restrict__ edge_row,
                 const int*   __restrict__ edge_col,
                 const float* __restrict__ edge_vals)
{
    int e = blockIdx.x * blockDim.x + threadIdx.x;
    if (e >= N_EDGES) return;
    const int r = edge_row[e];
    const int p = g_rowptr[r] + atomicAdd(&g_fill[r], 1);
    g_epack[p] = make_int2(edge_col[e], __float_as_int(edge_vals[e]));
}

// ---------------------------------------------------------------------------
// SpMM chunk: out[:, co:co+128] = relu(A @ xw[:, co:co+128] + bias)
// One warp per row; lane owns float4; 8-edge unroll for MLP.
// ---------------------------------------------------------------------------
__global__ __launch_bounds__(256)
void spmm_chunk_kernel(const float* __restrict__ bias,
                       float*       __restrict__ out,
                       int co)
{
    const int row  = (blockIdx.x * blockDim.x + threadIdx.x) >> 5;
    const int lane = threadIdx.x & 31;
    if (row >= N_NODES) return;

    const int s = g_rowptr[row];
    const int e = g_rowptr[row + 1];
    const int c = co + lane * 4;

    float4 acc = make_float4(0.f, 0.f, 0.f, 0.f);

    int i = s;
    for (; i + 7 < e; i += 8) {
        int2   p[8];
        float4 m[8];
        #pragma unroll
        for (int j = 0; j < 8; j++) p[j] = __ldg(&g_epack[i + j]);
        #pragma unroll
        for (int j = 0; j < 8; j++)
            m[j] = __ldg(reinterpret_cast<const float4*>(&g_xw[(size_t)p[j].x * D_OUT + c]));
        #pragma unroll
        for (int j = 0; j < 8; j++) {
            const float v = __int_as_float(p[j].y);
            acc.x = fmaf(v, m[j].x, acc.x);
            acc.y = fmaf(v, m[j].y, acc.y);
            acc.z = fmaf(v, m[j].z, acc.z);
            acc.w = fmaf(v, m[j].w, acc.w);
        }
    }
    if (i + 3 < e) {
        int2   p[4];
        float4 m[4];
        #pragma unroll
        for (int j = 0; j < 4; j++) p[j] = __ldg(&g_epack[i + j]);
        #pragma unroll
        for (int j = 0; j < 4; j++)
            m[j] = __ldg(reinterpret_cast<const float4*>(&g_xw[(size_t)p[j].x * D_OUT + c]));
        #pragma unroll
        for (int j = 0; j < 4; j++) {
            const float v = __int_as_float(p[j].y);
            acc.x = fmaf(v, m[j].x, acc.x);
            acc.y = fmaf(v, m[j].y, acc.y);
            acc.z = fmaf(v, m[j].z, acc.z);
            acc.w = fmaf(v, m[j].w, acc.w);
        }
        i += 4;
    }
    for (; i < e; i++) {
        const int2 p = __ldg(&g_epack[i]);
        const float v = __int_as_float(p.y);
        const float4 m = __ldg(reinterpret_cast<const float4*>(&g_xw[(size_t)p.x * D_OUT + c]));
        acc.x = fmaf(v, m.x, acc.x);
        acc.y = fmaf(v, m.y, acc.y);
        acc.z = fmaf(v, m.z, acc.z);
        acc.w = fmaf(v, m.w, acc.w);
    }

    const float4 b = *reinterpret_cast<const float4*>(&bias[c]);
    acc.x = fmaxf(acc.x + b.x, 0.f);
    acc.y = fmaxf(acc.y + b.y, 0.f);
    acc.z = fmaxf(acc.z + b.z, 0.f);
    acc.w = fmaxf(acc.w + b.w, 0.f);

    *reinterpret_cast<float4*>(&out[(size_t)row * D_OUT + c]) = acc;
}

// ---------------------------------------------------------------------------
// Launch: 2-stage pipeline.
//   side stream : GEMM chunk 0, GEMM chunk 1   (event after each)
//   main stream : CSR build (|| G0), then S0 (|| G1), then S1
// ---------------------------------------------------------------------------
static cudaStream_t g_side = nullptr;
static cudaEvent_t  g_fork = nullptr;
static cudaEvent_t  g_ev[N_CHUNKS] = {nullptr, nullptr};

extern "C" void kernel_launch(void* const* d_in, const int* in_sizes, int n_in,
                              void* d_out, int out_size)
{
    const float* x         = (const float*)d_in[0];
    const int*   edge_row  = (const int*)  d_in[1];
    const int*   edge_col  = (const int*)  d_in[2];
    const float* edge_vals = (const float*)d_in[3];
    const float* weight    = (const float*)d_in[4];
    const float* bias      = (const float*)d_in[5];
    float* out = (float*)d_out;

    if (g_side == nullptr) {
        cudaStreamCreateWithFlags(&g_side, cudaStreamNonBlocking);
        cudaEventCreateWithFlags(&g_fork, cudaEventDisableTiming);
        for (int k = 0; k < N_CHUNKS; k++)
            cudaEventCreateWithFlags(&g_ev[k], cudaEventDisableTiming);
    }

    // Fork side stream
    cudaEventRecord(g_fork, 0);
    cudaStreamWaitEvent(g_side, g_fork, 0);

    // Side: GEMM chunks
    const int gemm_blocks = (N_NODES + GBM - 1) / GBM;
    for (int k = 0; k < N_CHUNKS; k++) {
        gemm_chunk_kernel<<<gemm_blocks, 256, 0, g_side>>>(x, weight, k * CHUNK_COLS);
        cudaEventRecord(g_ev[k], g_side);
    }

    // Main: CSR build (overlaps GEMM chunk 0)
    zero_counts_kernel<<<(N_NODES + 255) / 256, 256>>>();
    count_kernel<<<(N_EDGES + 255) / 256, 256>>>(edge_row);
    scan_kernel<<<1, 1024>>>();
    fill_kernel<<<(N_EDGES + 255) / 256, 256>>>(edge_row, edge_col, edge_vals);

    // Main: SpMM chunks, each gated on its GEMM chunk
    const int spmm_blocks = (N_NODES * 32 + 255) / 256;
    for (int k = 0; k < N_CHUNKS; k++) {
        cudaStreamWaitEvent(0, g_ev[k], 0);
        spmm_chunk_kernel<<<spmm_blocks, 256>>>(bias, out, k * CHUNK_COLS);
    }
}

// round 6
// speedup vs baseline: 1.2945x; 1.1161x over previous
#include <cuda_runtime.h>
#include <cuda_fp16.h>
#include <cstdint>

#define N_NODES 50000
#define N_EDGES 800000
#define D_IN    256
#define D_OUT   256

#define N_CHUNKS   2
#define CHUNK_COLS 128

// ---------------- static device scratch (no allocations) -------------------
__device__ __half g_xwh[(size_t)N_NODES * D_OUT];  // 25.6 MB (fp16 xw)
__device__ int    g_deg[N_NODES];
__device__ int    g_fill[N_NODES];
__device__ int    g_rowptr[N_NODES + 1];
__device__ int2   g_epack[N_EDGES];                // {col, bitcast(val)}

// ---------------------------------------------------------------------------
// GEMM chunk: xwh[:, col0:col0+128] = (half) x @ W[:, col0:col0+128]
// 64x128 tile, BK=16, 256 threads, 8x4 microtile, double-buffered smem.
// fp32 accumulate; single rounding to fp16 at store.
// ---------------------------------------------------------------------------
#define GBM 64
#define GBN 128
#define GBK 16
#define APAD 68

__global__ __launch_bounds__(256)
void gemm_chunk_kernel(const float* __restrict__ x,
                       const float* __restrict__ W,
                       int col0)
{
    __shared__ float As[2][GBK][APAD];
    __shared__ float Bs[2][GBK][GBN];

    const int t    = threadIdx.x;
    const int row0 = blockIdx.x * GBM;

    const int a_m = t >> 2;            // 0..63
    const int a_k = (t & 3) * 4;       // 0,4,8,12
    const int b_k = t >> 5;            // 0..7 (and +8)
    const int b_n = (t & 31) * 4;      // 0..124

    const int ty = t >> 5;             // rows ty*8 .. ty*8+7
    const int tx = t & 31;             // cols tx*4

    const int gm_a  = row0 + a_m;
    const bool a_ok = (gm_a < N_NODES);
    const float* a_ptr = x + (size_t)gm_a * D_IN + a_k;

    float acc[8][4];
    #pragma unroll
    for (int i = 0; i < 8; i++)
        #pragma unroll
        for (int j = 0; j < 4; j++) acc[i][j] = 0.f;

    float4 ra = make_float4(0.f, 0.f, 0.f, 0.f);
    if (a_ok) ra = *reinterpret_cast<const float4*>(a_ptr);
    float4 rb0 = *reinterpret_cast<const float4*>(&W[(size_t)b_k * D_OUT + col0 + b_n]);
    float4 rb1 = *reinterpret_cast<const float4*>(&W[(size_t)(b_k + 8) * D_OUT + col0 + b_n]);

    As[0][a_k + 0][a_m] = ra.x;
    As[0][a_k + 1][a_m] = ra.y;
    As[0][a_k + 2][a_m] = ra.z;
    As[0][a_k + 3][a_m] = ra.w;
    *reinterpret_cast<float4*>(&Bs[0][b_k][b_n])     = rb0;
    *reinterpret_cast<float4*>(&Bs[0][b_k + 8][b_n]) = rb1;
    __syncthreads();

    int buf = 0;
    const int NSTEPS = D_IN / GBK;

    for (int s = 0; s < NSTEPS; s++) {
        float4 na, nb0, nb1;
        if (s < NSTEPS - 1) {
            const int kn = (s + 1) * GBK;
            na = make_float4(0.f, 0.f, 0.f, 0.f);
            if (a_ok) na = *reinterpret_cast<const float4*>(a_ptr + kn);
            nb0 = *reinterpret_cast<const float4*>(&W[(size_t)(kn + b_k) * D_OUT + col0 + b_n]);
            nb1 = *reinterpret_cast<const float4*>(&W[(size_t)(kn + b_k + 8) * D_OUT + col0 + b_n]);
        }

        #pragma unroll
        for (int k = 0; k < GBK; k++) {
            float a[8], b[4];
            *reinterpret_cast<float4*>(&a[0]) = *reinterpret_cast<const float4*>(&As[buf][k][ty * 8]);
            *reinterpret_cast<float4*>(&a[4]) = *reinterpret_cast<const float4*>(&As[buf][k][ty * 8 + 4]);
            *reinterpret_cast<float4*>(&b[0]) = *reinterpret_cast<const float4*>(&Bs[buf][k][tx * 4]);
            #pragma unroll
            for (int i = 0; i < 8; i++)
                #pragma unroll
                for (int j = 0; j < 4; j++)
                    acc[i][j] = fmaf(a[i], b[j], acc[i][j]);
        }

        if (s < NSTEPS - 1) {
            const int nb = buf ^ 1;
            As[nb][a_k + 0][a_m] = na.x;
            As[nb][a_k + 1][a_m] = na.y;
            As[nb][a_k + 2][a_m] = na.z;
            As[nb][a_k + 3][a_m] = na.w;
            *reinterpret_cast<float4*>(&Bs[nb][b_k][b_n])     = nb0;
            *reinterpret_cast<float4*>(&Bs[nb][b_k + 8][b_n]) = nb1;
            __syncthreads();
            buf = nb;
        }
    }

    #pragma unroll
    for (int i = 0; i < 8; i++) {
        const int gm = row0 + ty * 8 + i;
        if (gm < N_NODES) {
            const __half2 h01 = __floats2half2_rn(acc[i][0], acc[i][1]);
            const __half2 h23 = __floats2half2_rn(acc[i][2], acc[i][3]);
            uint2 u;
            u.x = *reinterpret_cast<const unsigned int*>(&h01);
            u.y = *reinterpret_cast<const unsigned int*>(&h23);
            *reinterpret_cast<uint2*>(&g_xwh[(size_t)gm * D_OUT + col0 + tx * 4]) = u;
        }
    }
}

// ---------------------------------------------------------------------------
// CSR construction
// ---------------------------------------------------------------------------
__global__ __launch_bounds__(256)
void zero_counts_kernel()
{
    int i = blockIdx.x * blockDim.x + threadIdx.x;
    if (i < N_NODES) { g_deg[i] = 0; g_fill[i] = 0; }
}

__global__ __launch_bounds__(256)
void count_kernel(const int* __restrict__ edge_row)
{
    int e = blockIdx.x * blockDim.x + threadIdx.x;
    if (e < N_EDGES) atomicAdd(&g_deg[edge_row[e]], 1);
}

__global__ __launch_bounds__(1024)
void scan_kernel()
{
    __shared__ int partial[1024];
    const int t = threadIdx.x;
    const int CHUNK = (N_NODES + 1023) / 1024;
    const int base = t * CHUNK;

    int s = 0;
    for (int i = 0; i < CHUNK; i++) {
        int idx = base + i;
        if (idx < N_NODES) s += g_deg[idx];
    }
    partial[t] = s;
    __syncthreads();

    for (int off = 1; off < 1024; off <<= 1) {
        int v = (t >= off) ? partial[t - off] : 0;
        __syncthreads();
        partial[t] += v;
        __syncthreads();
    }

    int run = (t == 0) ? 0 : partial[t - 1];
    for (int i = 0; i < CHUNK; i++) {
        int idx = base + i;
        if (idx < N_NODES) { g_rowptr[idx] = run; run += g_deg[idx]; }
    }
    if (t == 1023) g_rowptr[N_NODES] = partial[1023];
}

__global__ __launch_bounds__(256)
void fill_kernel(const int*   __restrict__ edge_row,
                 const int*   __restrict__ edge_col,
                 const float* __restrict__ edge_vals)
{
    int e = blockIdx.x * blockDim.x + threadIdx.x;
    if (e >= N_EDGES) return;
    const int r = edge_row[e];
    const int p = g_rowptr[r] + atomicAdd(&g_fill[r], 1);
    g_epack[p] = make_int2(edge_col[e], __float_as_int(edge_vals[e]));
}

// ---------------------------------------------------------------------------
// SpMM chunk: out[:, co:co+128] = relu(A @ xwh[:, co:co+128] + bias)
// One warp per row; lane owns 4 halves (8B); 8-edge unroll for MLP.
// fp32 accumulation.
// ---------------------------------------------------------------------------
__device__ __forceinline__ void fma_half4(float4& acc, float v, uint2 m)
{
    const __half2 h01 = *reinterpret_cast<const __half2*>(&m.x);
    const __half2 h23 = *reinterpret_cast<const __half2*>(&m.y);
    const float2 f01 = __half22float2(h01);
    const float2 f23 = __half22float2(h23);
    acc.x = fmaf(v, f01.x, acc.x);
    acc.y = fmaf(v, f01.y, acc.y);
    acc.z = fmaf(v, f23.x, acc.z);
    acc.w = fmaf(v, f23.y, acc.w);
}

__global__ __launch_bounds__(256)
void spmm_chunk_kernel(const float* __restrict__ bias,
                       float*       __restrict__ out,
                       int co)
{
    const int row  = (blockIdx.x * blockDim.x + threadIdx.x) >> 5;
    const int lane = threadIdx.x & 31;
    if (row >= N_NODES) return;

    const int s = g_rowptr[row];
    const int e = g_rowptr[row + 1];
    const int c = co + lane * 4;

    float4 acc = make_float4(0.f, 0.f, 0.f, 0.f);

    int i = s;
    for (; i + 7 < e; i += 8) {
        int2  p[8];
        uint2 m[8];
        #pragma unroll
        for (int j = 0; j < 8; j++) p[j] = __ldg(&g_epack[i + j]);
        #pragma unroll
        for (int j = 0; j < 8; j++)
            m[j] = __ldg(reinterpret_cast<const uint2*>(&g_xwh[(size_t)p[j].x * D_OUT + c]));
        #pragma unroll
        for (int j = 0; j < 8; j++)
            fma_half4(acc, __int_as_float(p[j].y), m[j]);
    }
    if (i + 3 < e) {
        int2  p[4];
        uint2 m[4];
        #pragma unroll
        for (int j = 0; j < 4; j++) p[j] = __ldg(&g_epack[i + j]);
        #pragma unroll
        for (int j = 0; j < 4; j++)
            m[j] = __ldg(reinterpret_cast<const uint2*>(&g_xwh[(size_t)p[j].x * D_OUT + c]));
        #pragma unroll
        for (int j = 0; j < 4; j++)
            fma_half4(acc, __int_as_float(p[j].y), m[j]);
        i += 4;
    }
    for (; i < e; i++) {
        const int2 p = __ldg(&g_epack[i]);
        const uint2 m = __ldg(reinterpret_cast<const uint2*>(&g_xwh[(size_t)p.x * D_OUT + c]));
        fma_half4(acc, __int_as_float(p.y), m);
    }

    const float4 b = *reinterpret_cast<const float4*>(&bias[c]);
    acc.x = fmaxf(acc.x + b.x, 0.f);
    acc.y = fmaxf(acc.y + b.y, 0.f);
    acc.z = fmaxf(acc.z + b.z, 0.f);
    acc.w = fmaxf(acc.w + b.w, 0.f);

    *reinterpret_cast<float4*>(&out[(size_t)row * D_OUT + c]) = acc;
}

// ---------------------------------------------------------------------------
// Launch: 2-stage pipeline.
//   side stream : GEMM chunk 0, GEMM chunk 1   (event after each)
//   main stream : CSR build (|| G0), then S0 (|| G1), then S1
// ---------------------------------------------------------------------------
static cudaStream_t g_side = nullptr;
static cudaEvent_t  g_fork = nullptr;
static cudaEvent_t  g_ev[N_CHUNKS] = {nullptr, nullptr};

extern "C" void kernel_launch(void* const* d_in, const int* in_sizes, int n_in,
                              void* d_out, int out_size)
{
    const float* x         = (const float*)d_in[0];
    const int*   edge_row  = (const int*)  d_in[1];
    const int*   edge_col  = (const int*)  d_in[2];
    const float* edge_vals = (const float*)d_in[3];
    const float* weight    = (const float*)d_in[4];
    const float* bias      = (const float*)d_in[5];
    float* out = (float*)d_out;

    if (g_side == nullptr) {
        cudaStreamCreateWithFlags(&g_side, cudaStreamNonBlocking);
        cudaEventCreateWithFlags(&g_fork, cudaEventDisableTiming);
        for (int k = 0; k < N_CHUNKS; k++)
            cudaEventCreateWithFlags(&g_ev[k], cudaEventDisableTiming);
    }

    // Fork side stream
    cudaEventRecord(g_fork, 0);
    cudaStreamWaitEvent(g_side, g_fork, 0);

    // Side: GEMM chunks
    const int gemm_blocks = (N_NODES + GBM - 1) / GBM;
    for (int k = 0; k < N_CHUNKS; k++) {
        gemm_chunk_kernel<<<gemm_blocks, 256, 0, g_side>>>(x, weight, k * CHUNK_COLS);
        cudaEventRecord(g_ev[k], g_side);
    }

    // Main: CSR build (overlaps GEMM chunk 0)
    zero_counts_kernel<<<(N_NODES + 255) / 256, 256>>>();
    count_kernel<<<(N_EDGES + 255) / 256, 256>>>(edge_row);
    scan_kernel<<<1, 1024>>>();
    fill_kernel<<<(N_EDGES + 255) / 256, 256>>>(edge_row, edge_col, edge_vals);

    // Main: SpMM chunks, each gated on its GEMM chunk
    const int spmm_blocks = (N_NODES * 32 + 255) / 256;
    for (int k = 0; k < N_CHUNKS; k++) {
        cudaStreamWaitEvent(0, g_ev[k], 0);
        spmm_chunk_kernel<<<spmm_blocks, 256>>>(bias, out, k * CHUNK_COLS);
    }
}

// round 7
// speedup vs baseline: 1.4195x; 1.0966x over previous
#include <cuda_runtime.h>
#include <cuda_fp16.h>
#include <mma.h>
#include <cstdint>

using namespace nvcuda;

#define N_NODES   50000
#define PAD_NODES 50048        // multiple of 128 (GEMM M-tile)
#define N_EDGES   800000
#define D_IN      256
#define D_OUT     256

#define N_CHUNKS   2
#define CHUNK_COLS 128

// ---------------- static device scratch (no allocations) -------------------
__device__ __align__(16) __half g_xh [(size_t)PAD_NODES * D_IN];   // x in fp16 (padded)
__device__ __align__(16) __half g_wh [(size_t)D_IN * D_OUT];       // W in fp16
__device__ __align__(16) __half g_xwh[(size_t)PAD_NODES * D_OUT];  // xw in fp16
__device__ int  g_deg[N_NODES];
__device__ int  g_fill[N_NODES];
__device__ int  g_rowptr[N_NODES + 1];
__device__ int2 g_epack[N_EDGES];                                   // {col, bitcast(val)}

// ---------------------------------------------------------------------------
// fp32 -> fp16 converters (pad rows zero-filled)
// ---------------------------------------------------------------------------
__global__ __launch_bounds__(256)
void convert_x_kernel(const float* __restrict__ x)
{
    const size_t idx = (size_t)blockIdx.x * blockDim.x + threadIdx.x;   // one per 4 elems
    const size_t i4  = idx * 4;
    if (i4 >= (size_t)PAD_NODES * D_IN) return;

    uint2 u;
    if (i4 < (size_t)N_NODES * D_IN) {
        const float4 v = *reinterpret_cast<const float4*>(&x[i4]);
        const __half2 h01 = __floats2half2_rn(v.x, v.y);
        const __half2 h23 = __floats2half2_rn(v.z, v.w);
        u.x = *reinterpret_cast<const unsigned int*>(&h01);
        u.y = *reinterpret_cast<const unsigned int*>(&h23);
    } else {
        u.x = 0u; u.y = 0u;
    }
    *reinterpret_cast<uint2*>(&g_xh[i4]) = u;
}

__global__ __launch_bounds__(256)
void convert_w_kernel(const float* __restrict__ W)
{
    const size_t idx = (size_t)blockIdx.x * blockDim.x + threadIdx.x;
    const size_t i4  = idx * 4;
    if (i4 >= (size_t)D_IN * D_OUT) return;
    const float4 v = *reinterpret_cast<const float4*>(&W[i4]);
    const __half2 h01 = __floats2half2_rn(v.x, v.y);
    const __half2 h23 = __floats2half2_rn(v.z, v.w);
    uint2 u;
    u.x = *reinterpret_cast<const unsigned int*>(&h01);
    u.y = *reinterpret_cast<const unsigned int*>(&h23);
    *reinterpret_cast<uint2*>(&g_wh[i4]) = u;
}

// ---------------------------------------------------------------------------
// WMMA GEMM chunk: xwh[:, col0:col0+128] = xh @ wh[:, col0:col0+128]
// Block = 128(M) x 128(N), 8 warps; warp tile = 32(M) x 64(N) = 2x4 frags.
// fp16 inputs, fp32 accumulate, fp16 store.
// ---------------------------------------------------------------------------
__global__ __launch_bounds__(256)
void wmma_gemm_kernel(int col0)
{
    const int warp = threadIdx.x >> 5;
    const int lane = threadIdx.x & 31;
    const int wm   = warp & 3;                 // 0..3  (M position)
    const int wn   = warp >> 2;                // 0..1  (N position)
    const int row0 = blockIdx.x * 128 + wm * 32;
    const int c0   = col0 + wn * 64;

    wmma::fragment<wmma::accumulator, 16, 16, 16, float> acc[2][4];
    #pragma unroll
    for (int i = 0; i < 2; i++)
        #pragma unroll
        for (int j = 0; j < 4; j++)
            wmma::fill_fragment(acc[i][j], 0.0f);

    for (int k = 0; k < D_IN; k += 16) {
        wmma::fragment<wmma::matrix_a, 16, 16, 16, __half, wmma::row_major> a0, a1;
        wmma::load_matrix_sync(a0, &g_xh[(size_t)row0 * D_IN + k], D_IN);
        wmma::load_matrix_sync(a1, &g_xh[(size_t)(row0 + 16) * D_IN + k], D_IN);
        #pragma unroll
        for (int j = 0; j < 4; j++) {
            wmma::fragment<wmma::matrix_b, 16, 16, 16, __half, wmma::row_major> b;
            wmma::load_matrix_sync(b, &g_wh[(size_t)k * D_OUT + c0 + j * 16], D_OUT);
            wmma::mma_sync(acc[0][j], a0, b, acc[0][j]);
            wmma::mma_sync(acc[1][j], a1, b, acc[1][j]);
        }
    }

    // Stage each 16x16 fp32 frag in smem, convert to fp16, vector-store.
    __shared__ float buf[8][16 * 16];
    const int r  = lane >> 1;              // 0..15
    const int cc = (lane & 1) * 8;         // 0 or 8

    #pragma unroll
    for (int i = 0; i < 2; i++) {
        #pragma unroll
        for (int j = 0; j < 4; j++) {
            wmma::store_matrix_sync(buf[warp], acc[i][j], 16, wmma::mem_row_major);
            __syncwarp();
            const int grow = row0 + i * 16 + r;
            if (grow < N_NODES) {
                union { __half h[8]; uint4 u; } pk;
                #pragma unroll
                for (int t = 0; t < 8; t++)
                    pk.h[t] = __float2half(buf[warp][r * 16 + cc + t]);
                *reinterpret_cast<uint4*>(&g_xwh[(size_t)grow * D_OUT + c0 + j * 16 + cc]) = pk.u;
            }
            __syncwarp();
        }
    }
}

// ---------------------------------------------------------------------------
// CSR construction
// ---------------------------------------------------------------------------
__global__ __launch_bounds__(256)
void zero_counts_kernel()
{
    int i = blockIdx.x * blockDim.x + threadIdx.x;
    if (i < N_NODES) { g_deg[i] = 0; g_fill[i] = 0; }
}

__global__ __launch_bounds__(256)
void count_kernel(const int* __restrict__ edge_row)
{
    int e = blockIdx.x * blockDim.x + threadIdx.x;
    if (e < N_EDGES) atomicAdd(&g_deg[edge_row[e]], 1);
}

__global__ __launch_bounds__(1024)
void scan_kernel()
{
    __shared__ int partial[1024];
    const int t = threadIdx.x;
    const int CHUNK = (N_NODES + 1023) / 1024;
    const int base = t * CHUNK;

    int s = 0;
    for (int i = 0; i < CHUNK; i++) {
        int idx = base + i;
        if (idx < N_NODES) s += g_deg[idx];
    }
    partial[t] = s;
    __syncthreads();

    for (int off = 1; off < 1024; off <<= 1) {
        int v = (t >= off) ? partial[t - off] : 0;
        __syncthreads();
        partial[t] += v;
        __syncthreads();
    }

    int run = (t == 0) ? 0 : partial[t - 1];
    for (int i = 0; i < CHUNK; i++) {
        int idx = base + i;
        if (idx < N_NODES) { g_rowptr[idx] = run; run += g_deg[idx]; }
    }
    if (t == 1023) g_rowptr[N_NODES] = partial[1023];
}

__global__ __launch_bounds__(256)
void fill_kernel(const int*   __restrict__ edge_row,
                 const int*   __restrict__ edge_col,
                 const float* __restrict__ edge_vals)
{
    int e = blockIdx.x * blockDim.x + threadIdx.x;
    if (e >= N_EDGES) return;
    const int r = edge_row[e];
    const int p = g_rowptr[r] + atomicAdd(&g_fill[r], 1);
    g_epack[p] = make_int2(edge_col[e], __float_as_int(edge_vals[e]));
}

// ---------------------------------------------------------------------------
// SpMM chunk: out[:, co:co+128] = relu(A @ xwh[:, co:co+128] + bias)
// One warp per row; lane owns 4 halves (8B); 8-edge unroll; fp32 accumulate.
// ---------------------------------------------------------------------------
__device__ __forceinline__ void fma_half4(float4& acc, float v, uint2 m)
{
    const __half2 h01 = *reinterpret_cast<const __half2*>(&m.x);
    const __half2 h23 = *reinterpret_cast<const __half2*>(&m.y);
    const float2 f01 = __half22float2(h01);
    const float2 f23 = __half22float2(h23);
    acc.x = fmaf(v, f01.x, acc.x);
    acc.y = fmaf(v, f01.y, acc.y);
    acc.z = fmaf(v, f23.x, acc.z);
    acc.w = fmaf(v, f23.y, acc.w);
}

__global__ __launch_bounds__(256)
void spmm_chunk_kernel(const float* __restrict__ bias,
                       float*       __restrict__ out,
                       int co)
{
    const int row  = (blockIdx.x * blockDim.x + threadIdx.x) >> 5;
    const int lane = threadIdx.x & 31;
    if (row >= N_NODES) return;

    const int s = g_rowptr[row];
    const int e = g_rowptr[row + 1];
    const int c = co + lane * 4;

    float4 acc = make_float4(0.f, 0.f, 0.f, 0.f);

    int i = s;
    for (; i + 7 < e; i += 8) {
        int2  p[8];
        uint2 m[8];
        #pragma unroll
        for (int j = 0; j < 8; j++) p[j] = __ldg(&g_epack[i + j]);
        #pragma unroll
        for (int j = 0; j < 8; j++)
            m[j] = __ldg(reinterpret_cast<const uint2*>(&g_xwh[(size_t)p[j].x * D_OUT + c]));
        #pragma unroll
        for (int j = 0; j < 8; j++)
            fma_half4(acc, __int_as_float(p[j].y), m[j]);
    }
    if (i + 3 < e) {
        int2  p[4];
        uint2 m[4];
        #pragma unroll
        for (int j = 0; j < 4; j++) p[j] = __ldg(&g_epack[i + j]);
        #pragma unroll
        for (int j = 0; j < 4; j++)
            m[j] = __ldg(reinterpret_cast<const uint2*>(&g_xwh[(size_t)p[j].x * D_OUT + c]));
        #pragma unroll
        for (int j = 0; j < 4; j++)
            fma_half4(acc, __int_as_float(p[j].y), m[j]);
        i += 4;
    }
    for (; i < e; i++) {
        const int2 p = __ldg(&g_epack[i]);
        const uint2 m = __ldg(reinterpret_cast<const uint2*>(&g_xwh[(size_t)p.x * D_OUT + c]));
        fma_half4(acc, __int_as_float(p.y), m);
    }

    const float4 b = *reinterpret_cast<const float4*>(&bias[c]);
    acc.x = fmaxf(acc.x + b.x, 0.f);
    acc.y = fmaxf(acc.y + b.y, 0.f);
    acc.z = fmaxf(acc.z + b.z, 0.f);
    acc.w = fmaxf(acc.w + b.w, 0.f);

    *reinterpret_cast<float4*>(&out[(size_t)row * D_OUT + c]) = acc;
}

// ---------------------------------------------------------------------------
// Launch: 2-stage pipeline.
//   side stream : convert x/W, WMMA chunk 0, chunk 1  (event after each chunk)
//   main stream : CSR build (||), then S0 (|| G1), then S1
// ---------------------------------------------------------------------------
static cudaStream_t g_side = nullptr;
static cudaEvent_t  g_fork = nullptr;
static cudaEvent_t  g_ev[N_CHUNKS] = {nullptr, nullptr};

extern "C" void kernel_launch(void* const* d_in, const int* in_sizes, int n_in,
                              void* d_out, int out_size)
{
    const float* x         = (const float*)d_in[0];
    const int*   edge_row  = (const int*)  d_in[1];
    const int*   edge_col  = (const int*)  d_in[2];
    const float* edge_vals = (const float*)d_in[3];
    const float* weight    = (const float*)d_in[4];
    const float* bias      = (const float*)d_in[5];
    float* out = (float*)d_out;

    if (g_side == nullptr) {
        cudaStreamCreateWithFlags(&g_side, cudaStreamNonBlocking);
        cudaEventCreateWithFlags(&g_fork, cudaEventDisableTiming);
        for (int k = 0; k < N_CHUNKS; k++)
            cudaEventCreateWithFlags(&g_ev[k], cudaEventDisableTiming);
    }

    // Fork side stream
    cudaEventRecord(g_fork, 0);
    cudaStreamWaitEvent(g_side, g_fork, 0);

    // Side: fp16 conversion + WMMA GEMM chunks
    {
        const size_t nx4 = (size_t)PAD_NODES * D_IN / 4;
        convert_x_kernel<<<(int)((nx4 + 255) / 256), 256, 0, g_side>>>(x);
        const size_t nw4 = (size_t)D_IN * D_OUT / 4;
        convert_w_kernel<<<(int)((nw4 + 255) / 256), 256, 0, g_side>>>(weight);

        const int gemm_blocks = PAD_NODES / 128;
        for (int k = 0; k < N_CHUNKS; k++) {
            wmma_gemm_kernel<<<gemm_blocks, 256, 0, g_side>>>(k * CHUNK_COLS);
            cudaEventRecord(g_ev[k], g_side);
        }
    }

    // Main: CSR build (overlaps conversion + GEMM chunk 0)
    zero_counts_kernel<<<(N_NODES + 255) / 256, 256>>>();
    count_kernel<<<(N_EDGES + 255) / 256, 256>>>(edge_row);
    scan_kernel<<<1, 1024>>>();
    fill_kernel<<<(N_EDGES + 255) / 256, 256>>>(edge_row, edge_col, edge_vals);

    // Main: SpMM chunks, each gated on its GEMM chunk
    const int spmm_blocks = (N_NODES * 32 + 255) / 256;
    for (int k = 0; k < N_CHUNKS; k++) {
        cudaStreamWaitEvent(0, g_ev[k], 0);
        spmm_chunk_kernel<<<spmm_blocks, 256>>>(bias, out, k * CHUNK_COLS);
    }
}

// round 8
// speedup vs baseline: 1.5777x; 1.1114x over previous
#include <cuda_runtime.h>
#include <cuda_fp16.h>
#include <mma.h>
#include <cstdint>

using namespace nvcuda;

#define N_NODES   50000
#define PAD_NODES 50048        // multiple of 128 (GEMM M-tile)
#define N_EDGES   800000
#define D_IN      256
#define D_OUT     256

#define N_CHUNKS   2
#define CHUNK_COLS 128

// ---------------- static device scratch (no allocations) -------------------
__device__ __align__(16) __half g_xh [(size_t)PAD_NODES * D_IN];   // x in fp16 (padded)
__device__ __align__(16) __half g_wh [(size_t)D_IN * D_OUT];       // W in fp16
__device__ __align__(16) __half g_xwh[(size_t)PAD_NODES * D_OUT];  // xw in fp16
__device__ int  g_deg[N_NODES];
__device__ int  g_fill[N_NODES];
__device__ int  g_rowptr[N_NODES + 1];
__device__ int2 g_epack[N_EDGES];                                   // {col, bitcast(val)}

// ---------------------------------------------------------------------------
// fp32 -> fp16 converters (pad rows zero-filled)
// ---------------------------------------------------------------------------
__global__ __launch_bounds__(256)
void convert_x_kernel(const float* __restrict__ x)
{
    const size_t idx = (size_t)blockIdx.x * blockDim.x + threadIdx.x;
    const size_t i4  = idx * 4;
    if (i4 >= (size_t)PAD_NODES * D_IN) return;

    uint2 u;
    if (i4 < (size_t)N_NODES * D_IN) {
        const float4 v = *reinterpret_cast<const float4*>(&x[i4]);
        const __half2 h01 = __floats2half2_rn(v.x, v.y);
        const __half2 h23 = __floats2half2_rn(v.z, v.w);
        u.x = *reinterpret_cast<const unsigned int*>(&h01);
        u.y = *reinterpret_cast<const unsigned int*>(&h23);
    } else {
        u.x = 0u; u.y = 0u;
    }
    *reinterpret_cast<uint2*>(&g_xh[i4]) = u;
}

__global__ __launch_bounds__(256)
void convert_w_kernel(const float* __restrict__ W)
{
    const size_t idx = (size_t)blockIdx.x * blockDim.x + threadIdx.x;
    const size_t i4  = idx * 4;
    if (i4 >= (size_t)D_IN * D_OUT) return;
    const float4 v = *reinterpret_cast<const float4*>(&W[i4]);
    const __half2 h01 = __floats2half2_rn(v.x, v.y);
    const __half2 h23 = __floats2half2_rn(v.z, v.w);
    uint2 u;
    u.x = *reinterpret_cast<const unsigned int*>(&h01);
    u.y = *reinterpret_cast<const unsigned int*>(&h23);
    *reinterpret_cast<uint2*>(&g_wh[i4]) = u;
}

// ---------------------------------------------------------------------------
// HMMA GEMM chunk (smem-staged, double-buffered):
//   xwh[:, col0:col0+128] = xh @ wh[:, col0:col0+128]
// Block 128M x 128N, BK=32, 8 warps (4x2), warp tile 32x64 (2x4 frags).
// ---------------------------------------------------------------------------
#define BLK_M 128
#define BLK_K 32
#define A_LD  (BLK_K + 8)       // 40 halves
#define B_LD  (CHUNK_COLS + 8)  // 136 halves

__global__ __launch_bounds__(256)
void wmma_gemm_kernel(int col0)
{
    __shared__ __half As[2][BLK_M * A_LD];          // 2 * 128*40*2B = 20.0 KB
    __shared__ __half Bs[2][BLK_K * B_LD];          // 2 *  32*136*2B = 17.4 KB
    __shared__ float  ebuf[8][16 * 16];             // epilogue staging, 8 KB

    const int t    = threadIdx.x;
    const int warp = t >> 5;
    const int lane = t & 31;
    const int wm   = warp & 3;                      // 0..3 (M)
    const int wn   = warp >> 2;                     // 0..1 (N)
    const int row0 = blockIdx.x * BLK_M;

    // A tile: 128 rows x 32 halves = 512 uint4; 2 per thread
    const int a_row0 = t >> 1;                      // rows t/2 and t/2+... use idx scheme
    // B tile: 32 rows x 128 halves = 512 uint4; 2 per thread
    // generic idx mapping
    wmma::fragment<wmma::accumulator, 16, 16, 16, float> acc[2][4];
    #pragma unroll
    for (int i = 0; i < 2; i++)
        #pragma unroll
        for (int j = 0; j < 4; j++)
            wmma::fill_fragment(acc[i][j], 0.0f);

    // load helpers ------------------------------------------------------
    auto load_a_g = [&](int k0, uint4* r) {
        #pragma unroll
        for (int q = 0; q < 2; q++) {
            const int idx = t + q * 256;            // 0..511
            const int row = idx >> 2;               // /4
            const int c8  = (idx & 3) * 8;
            r[q] = *reinterpret_cast<const uint4*>(
                &g_xh[(size_t)(row0 + row) * D_IN + k0 + c8]);
        }
    };
    auto load_b_g = [&](int k0, uint4* r) {
        #pragma unroll
        for (int q = 0; q < 2; q++) {
            const int idx = t + q * 256;
            const int row = idx >> 4;               // /16
            const int c8  = (idx & 15) * 8;
            r[q] = *reinterpret_cast<const uint4*>(
                &g_wh[(size_t)(k0 + row) * D_OUT + col0 + c8]);
        }
    };
    auto store_a_s = [&](int buf, const uint4* r) {
        #pragma unroll
        for (int q = 0; q < 2; q++) {
            const int idx = t + q * 256;
            const int row = idx >> 2;
            const int c8  = (idx & 3) * 8;
            *reinterpret_cast<uint4*>(&As[buf][row * A_LD + c8]) = r[q];
        }
    };
    auto store_b_s = [&](int buf, const uint4* r) {
        #pragma unroll
        for (int q = 0; q < 2; q++) {
            const int idx = t + q * 256;
            const int row = idx >> 4;
            const int c8  = (idx & 15) * 8;
            *reinterpret_cast<uint4*>(&Bs[buf][row * B_LD + c8]) = r[q];
        }
    };

    // prologue
    uint4 ra[2], rb[2];
    load_a_g(0, ra);
    load_b_g(0, rb);
    store_a_s(0, ra);
    store_b_s(0, rb);
    __syncthreads();

    const int NSTEP = D_IN / BLK_K;                 // 8
    int buf = 0;

    for (int s = 0; s < NSTEP; s++) {
        if (s + 1 < NSTEP) {
            load_a_g((s + 1) * BLK_K, ra);
            load_b_g((s + 1) * BLK_K, rb);
        }

        #pragma unroll
        for (int kk = 0; kk < 2; kk++) {
            wmma::fragment<wmma::matrix_a, 16, 16, 16, __half, wmma::row_major> a0, a1;
            wmma::load_matrix_sync(a0, &As[buf][(wm * 32 +  0) * A_LD + kk * 16], A_LD);
            wmma::load_matrix_sync(a1, &As[buf][(wm * 32 + 16) * A_LD + kk * 16], A_LD);
            #pragma unroll
            for (int j = 0; j < 4; j++) {
                wmma::fragment<wmma::matrix_b, 16, 16, 16, __half, wmma::row_major> b;
                wmma::load_matrix_sync(b, &Bs[buf][(kk * 16) * B_LD + wn * 64 + j * 16], B_LD);
                wmma::mma_sync(acc[0][j], a0, b, acc[0][j]);
                wmma::mma_sync(acc[1][j], a1, b, acc[1][j]);
            }
        }

        if (s + 1 < NSTEP) {
            const int nb = buf ^ 1;
            store_a_s(nb, ra);
            store_b_s(nb, rb);
            __syncthreads();
            buf = nb;
        }
    }

    // epilogue: frag -> smem fp32 -> fp16 vector store
    const int r  = lane >> 1;
    const int cc = (lane & 1) * 8;
    const int c0 = col0 + wn * 64;

    #pragma unroll
    for (int i = 0; i < 2; i++) {
        #pragma unroll
        for (int j = 0; j < 4; j++) {
            wmma::store_matrix_sync(ebuf[warp], acc[i][j], 16, wmma::mem_row_major);
            __syncwarp();
            const int grow = row0 + wm * 32 + i * 16 + r;
            if (grow < N_NODES) {
                union { __half h[8]; uint4 u; } pk;
                #pragma unroll
                for (int q = 0; q < 8; q++)
                    pk.h[q] = __float2half(ebuf[warp][r * 16 + cc + q]);
                *reinterpret_cast<uint4*>(&g_xwh[(size_t)grow * D_OUT + c0 + j * 16 + cc]) = pk.u;
            }
            __syncwarp();
        }
    }
}

// ---------------------------------------------------------------------------
// CSR construction
// ---------------------------------------------------------------------------
__global__ __launch_bounds__(256)
void zero_counts_kernel()
{
    int i = blockIdx.x * blockDim.x + threadIdx.x;
    if (i < N_NODES) { g_deg[i] = 0; g_fill[i] = 0; }
}

__global__ __launch_bounds__(256)
void count_kernel(const int* __restrict__ edge_row)
{
    int e = blockIdx.x * blockDim.x + threadIdx.x;
    if (e < N_EDGES) atomicAdd(&g_deg[edge_row[e]], 1);
}

__global__ __launch_bounds__(1024)
void scan_kernel()
{
    __shared__ int partial[1024];
    const int t = threadIdx.x;
    const int CHUNK = (N_NODES + 1023) / 1024;
    const int base = t * CHUNK;

    int s = 0;
    for (int i = 0; i < CHUNK; i++) {
        int idx = base + i;
        if (idx < N_NODES) s += g_deg[idx];
    }
    partial[t] = s;
    __syncthreads();

    for (int off = 1; off < 1024; off <<= 1) {
        int v = (t >= off) ? partial[t - off] : 0;
        __syncthreads();
        partial[t] += v;
        __syncthreads();
    }

    int run = (t == 0) ? 0 : partial[t - 1];
    for (int i = 0; i < CHUNK; i++) {
        int idx = base + i;
        if (idx < N_NODES) { g_rowptr[idx] = run; run += g_deg[idx]; }
    }
    if (t == 1023) g_rowptr[N_NODES] = partial[1023];
}

__global__ __launch_bounds__(256)
void fill_kernel(const int*   __restrict__ edge_row,
                 const int*   __restrict__ edge_col,
                 const float* __restrict__ edge_vals)
{
    int e = blockIdx.x * blockDim.x + threadIdx.x;
    if (e >= N_EDGES) return;
    const int r = edge_row[e];
    const int p = g_rowptr[r] + atomicAdd(&g_fill[r], 1);
    g_epack[p] = make_int2(edge_col[e], __float_as_int(edge_vals[e]));
}

// ---------------------------------------------------------------------------
// SpMM chunk: out[:, co:co+128] = relu(A @ xwh[:, co:co+128] + bias)
// One warp per row; lane owns 4 halves (8B); 8-edge unroll; fp32 accumulate.
// ---------------------------------------------------------------------------
__device__ __forceinline__ void fma_half4(float4& acc, float v, uint2 m)
{
    const __half2 h01 = *reinterpret_cast<const __half2*>(&m.x);
    const __half2 h23 = *reinterpret_cast<const __half2*>(&m.y);
    const float2 f01 = __half22float2(h01);
    const float2 f23 = __half22float2(h23);
    acc.x = fmaf(v, f01.x, acc.x);
    acc.y = fmaf(v, f01.y, acc.y);
    acc.z = fmaf(v, f23.x, acc.z);
    acc.w = fmaf(v, f23.y, acc.w);
}

__global__ __launch_bounds__(256)
void spmm_chunk_kernel(const float* __restrict__ bias,
                       float*       __restrict__ out,
                       int co)
{
    const int row  = (blockIdx.x * blockDim.x + threadIdx.x) >> 5;
    const int lane = threadIdx.x & 31;
    if (row >= N_NODES) return;

    const int s = g_rowptr[row];
    const int e = g_rowptr[row + 1];
    const int c = co + lane * 4;

    float4 acc = make_float4(0.f, 0.f, 0.f, 0.f);

    int i = s;
    for (; i + 7 < e; i += 8) {
        int2  p[8];
        uint2 m[8];
        #pragma unroll
        for (int j = 0; j < 8; j++) p[j] = __ldg(&g_epack[i + j]);
        #pragma unroll
        for (int j = 0; j < 8; j++)
            m[j] = __ldg(reinterpret_cast<const uint2*>(&g_xwh[(size_t)p[j].x * D_OUT + c]));
        #pragma unroll
        for (int j = 0; j < 8; j++)
            fma_half4(acc, __int_as_float(p[j].y), m[j]);
    }
    if (i + 3 < e) {
        int2  p[4];
        uint2 m[4];
        #pragma unroll
        for (int j = 0; j < 4; j++) p[j] = __ldg(&g_epack[i + j]);
        #pragma unroll
        for (int j = 0; j < 4; j++)
            m[j] = __ldg(reinterpret_cast<const uint2*>(&g_xwh[(size_t)p[j].x * D_OUT + c]));
        #pragma unroll
        for (int j = 0; j < 4; j++)
            fma_half4(acc, __int_as_float(p[j].y), m[j]);
        i += 4;
    }
    for (; i < e; i++) {
        const int2 p = __ldg(&g_epack[i]);
        const uint2 m = __ldg(reinterpret_cast<const uint2*>(&g_xwh[(size_t)p.x * D_OUT + c]));
        fma_half4(acc, __int_as_float(p.y), m);
    }

    const float4 b = *reinterpret_cast<const float4*>(&bias[c]);
    acc.x = fmaxf(acc.x + b.x, 0.f);
    acc.y = fmaxf(acc.y + b.y, 0.f);
    acc.z = fmaxf(acc.z + b.z, 0.f);
    acc.w = fmaxf(acc.w + b.w, 0.f);

    *reinterpret_cast<float4*>(&out[(size_t)row * D_OUT + c]) = acc;
}

// ---------------------------------------------------------------------------
// Launch: 2-stage pipeline.
//   side stream : convert x/W, GEMM chunk 0, chunk 1  (event after each)
//   main stream : CSR build (||), then S0 (|| G1), then S1
// ---------------------------------------------------------------------------
static cudaStream_t g_side = nullptr;
static cudaEvent_t  g_fork = nullptr;
static cudaEvent_t  g_ev[N_CHUNKS] = {nullptr, nullptr};

extern "C" void kernel_launch(void* const* d_in, const int* in_sizes, int n_in,
                              void* d_out, int out_size)
{
    const float* x         = (const float*)d_in[0];
    const int*   edge_row  = (const int*)  d_in[1];
    const int*   edge_col  = (const int*)  d_in[2];
    const float* edge_vals = (const float*)d_in[3];
    const float* weight    = (const float*)d_in[4];
    const float* bias      = (const float*)d_in[5];
    float* out = (float*)d_out;

    if (g_side == nullptr) {
        cudaStreamCreateWithFlags(&g_side, cudaStreamNonBlocking);
        cudaEventCreateWithFlags(&g_fork, cudaEventDisableTiming);
        for (int k = 0; k < N_CHUNKS; k++)
            cudaEventCreateWithFlags(&g_ev[k], cudaEventDisableTiming);
    }

    // Fork side stream
    cudaEventRecord(g_fork, 0);
    cudaStreamWaitEvent(g_side, g_fork, 0);

    // Side: fp16 conversion + GEMM chunks
    {
        const size_t nx4 = (size_t)PAD_NODES * D_IN / 4;
        convert_x_kernel<<<(int)((nx4 + 255) / 256), 256, 0, g_side>>>(x);
        const size_t nw4 = (size_t)D_IN * D_OUT / 4;
        convert_w_kernel<<<(int)((nw4 + 255) / 256), 256, 0, g_side>>>(weight);

        const int gemm_blocks = PAD_NODES / BLK_M;
        for (int k = 0; k < N_CHUNKS; k++) {
            wmma_gemm_kernel<<<gemm_blocks, 256, 0, g_side>>>(k * CHUNK_COLS);
            cudaEventRecord(g_ev[k], g_side);
        }
    }

    // Main: CSR build (overlaps conversion + GEMM chunk 0)
    zero_counts_kernel<<<(N_NODES + 255) / 256, 256>>>();
    count_kernel<<<(N_EDGES + 255) / 256, 256>>>(edge_row);
    scan_kernel<<<1, 1024>>>();
    fill_kernel<<<(N_EDGES + 255) / 256, 256>>>(edge_row, edge_col, edge_vals);

    // Main: SpMM chunks, each gated on its GEMM chunk
    const int spmm_blocks = (N_NODES * 32 + 255) / 256;
    for (int k = 0; k < N_CHUNKS; k++) {
        cudaStreamWaitEvent(0, g_ev[k], 0);
        spmm_chunk_kernel<<<spmm_blocks, 256>>>(bias, out, k * CHUNK_COLS);
    }
}

// round 9
// speedup vs baseline: 1.5800x; 1.0015x over previous
#include <cuda_runtime.h>
#include <cuda_fp16.h>
#include <mma.h>
#include <cstdint>

using namespace nvcuda;

#define N_NODES   50000
#define PAD_NODES 50048        // multiple of 128 (GEMM M-tile)
#define N_EDGES   800000
#define D_IN      256
#define D_OUT     256

#define N_CHUNKS   2
#define CHUNK_COLS 128

// ---------------- static device scratch (no allocations) -------------------
__device__ __align__(16) __half g_xh [(size_t)PAD_NODES * D_IN];   // x in fp16 (padded)
__device__ __align__(16) __half g_wh [(size_t)D_IN * D_OUT];       // W in fp16
__device__ __align__(16) __half g_xwh[(size_t)PAD_NODES * D_OUT];  // xw in fp16
__device__ int  g_deg[N_NODES];
__device__ int  g_fill[N_NODES];
__device__ int  g_rowptr[N_NODES + 1];
__device__ int2 g_epack[N_EDGES];                                   // {col, bitcast(val)}

// ---------------------------------------------------------------------------
// fp32 -> fp16 converters (pad rows zero-filled)
// ---------------------------------------------------------------------------
__global__ __launch_bounds__(256)
void convert_x_kernel(const float* __restrict__ x)
{
    const size_t idx = (size_t)blockIdx.x * blockDim.x + threadIdx.x;
    const size_t i4  = idx * 4;
    if (i4 >= (size_t)PAD_NODES * D_IN) return;

    uint2 u;
    if (i4 < (size_t)N_NODES * D_IN) {
        const float4 v = *reinterpret_cast<const float4*>(&x[i4]);
        const __half2 h01 = __floats2half2_rn(v.x, v.y);
        const __half2 h23 = __floats2half2_rn(v.z, v.w);
        u.x = *reinterpret_cast<const unsigned int*>(&h01);
        u.y = *reinterpret_cast<const unsigned int*>(&h23);
    } else {
        u.x = 0u; u.y = 0u;
    }
    *reinterpret_cast<uint2*>(&g_xh[i4]) = u;
}

__global__ __launch_bounds__(256)
void convert_w_kernel(const float* __restrict__ W)
{
    const size_t idx = (size_t)blockIdx.x * blockDim.x + threadIdx.x;
    const size_t i4  = idx * 4;
    if (i4 >= (size_t)D_IN * D_OUT) return;
    const float4 v = *reinterpret_cast<const float4*>(&W[i4]);
    const __half2 h01 = __floats2half2_rn(v.x, v.y);
    const __half2 h23 = __floats2half2_rn(v.z, v.w);
    uint2 u;
    u.x = *reinterpret_cast<const unsigned int*>(&h01);
    u.y = *reinterpret_cast<const unsigned int*>(&h23);
    *reinterpret_cast<uint2*>(&g_wh[i4]) = u;
}

// ---------------------------------------------------------------------------
// HMMA GEMM chunk (smem-staged, double-buffered) — unchanged from R7.
// ---------------------------------------------------------------------------
#define BLK_M 128
#define BLK_K 32
#define A_LD  (BLK_K + 8)
#define B_LD  (CHUNK_COLS + 8)

__global__ __launch_bounds__(256)
void wmma_gemm_kernel(int col0)
{
    __shared__ __half As[2][BLK_M * A_LD];
    __shared__ __half Bs[2][BLK_K * B_LD];
    __shared__ float  ebuf[8][16 * 16];

    const int t    = threadIdx.x;
    const int warp = t >> 5;
    const int lane = t & 31;
    const int wm   = warp & 3;
    const int wn   = warp >> 2;
    const int row0 = blockIdx.x * BLK_M;

    wmma::fragment<wmma::accumulator, 16, 16, 16, float> acc[2][4];
    #pragma unroll
    for (int i = 0; i < 2; i++)
        #pragma unroll
        for (int j = 0; j < 4; j++)
            wmma::fill_fragment(acc[i][j], 0.0f);

    auto load_a_g = [&](int k0, uint4* r) {
        #pragma unroll
        for (int q = 0; q < 2; q++) {
            const int idx = t + q * 256;
            const int row = idx >> 2;
            const int c8  = (idx & 3) * 8;
            r[q] = *reinterpret_cast<const uint4*>(
                &g_xh[(size_t)(row0 + row) * D_IN + k0 + c8]);
        }
    };
    auto load_b_g = [&](int k0, uint4* r) {
        #pragma unroll
        for (int q = 0; q < 2; q++) {
            const int idx = t + q * 256;
            const int row = idx >> 4;
            const int c8  = (idx & 15) * 8;
            r[q] = *reinterpret_cast<const uint4*>(
                &g_wh[(size_t)(k0 + row) * D_OUT + col0 + c8]);
        }
    };
    auto store_a_s = [&](int buf, const uint4* r) {
        #pragma unroll
        for (int q = 0; q < 2; q++) {
            const int idx = t + q * 256;
            const int row = idx >> 2;
            const int c8  = (idx & 3) * 8;
            *reinterpret_cast<uint4*>(&As[buf][row * A_LD + c8]) = r[q];
        }
    };
    auto store_b_s = [&](int buf, const uint4* r) {
        #pragma unroll
        for (int q = 0; q < 2; q++) {
            const int idx = t + q * 256;
            const int row = idx >> 4;
            const int c8  = (idx & 15) * 8;
            *reinterpret_cast<uint4*>(&Bs[buf][row * B_LD + c8]) = r[q];
        }
    };

    uint4 ra[2], rb[2];
    load_a_g(0, ra);
    load_b_g(0, rb);
    store_a_s(0, ra);
    store_b_s(0, rb);
    __syncthreads();

    const int NSTEP = D_IN / BLK_K;
    int buf = 0;

    for (int s = 0; s < NSTEP; s++) {
        if (s + 1 < NSTEP) {
            load_a_g((s + 1) * BLK_K, ra);
            load_b_g((s + 1) * BLK_K, rb);
        }

        #pragma unroll
        for (int kk = 0; kk < 2; kk++) {
            wmma::fragment<wmma::matrix_a, 16, 16, 16, __half, wmma::row_major> a0, a1;
            wmma::load_matrix_sync(a0, &As[buf][(wm * 32 +  0) * A_LD + kk * 16], A_LD);
            wmma::load_matrix_sync(a1, &As[buf][(wm * 32 + 16) * A_LD + kk * 16], A_LD);
            #pragma unroll
            for (int j = 0; j < 4; j++) {
                wmma::fragment<wmma::matrix_b, 16, 16, 16, __half, wmma::row_major> b;
                wmma::load_matrix_sync(b, &Bs[buf][(kk * 16) * B_LD + wn * 64 + j * 16], B_LD);
                wmma::mma_sync(acc[0][j], a0, b, acc[0][j]);
                wmma::mma_sync(acc[1][j], a1, b, acc[1][j]);
            }
        }

        if (s + 1 < NSTEP) {
            const int nb = buf ^ 1;
            store_a_s(nb, ra);
            store_b_s(nb, rb);
            __syncthreads();
            buf = nb;
        }
    }

    const int r  = lane >> 1;
    const int cc = (lane & 1) * 8;
    const int c0 = col0 + wn * 64;

    #pragma unroll
    for (int i = 0; i < 2; i++) {
        #pragma unroll
        for (int j = 0; j < 4; j++) {
            wmma::store_matrix_sync(ebuf[warp], acc[i][j], 16, wmma::mem_row_major);
            __syncwarp();
            const int grow = row0 + wm * 32 + i * 16 + r;
            if (grow < N_NODES) {
                union { __half h[8]; uint4 u; } pk;
                #pragma unroll
                for (int q = 0; q < 8; q++)
                    pk.h[q] = __float2half(ebuf[warp][r * 16 + cc + q]);
                *reinterpret_cast<uint4*>(&g_xwh[(size_t)grow * D_OUT + c0 + j * 16 + cc]) = pk.u;
            }
            __syncwarp();
        }
    }
}

// ---------------------------------------------------------------------------
// CSR construction
// ---------------------------------------------------------------------------
__global__ __launch_bounds__(256)
void zero_counts_kernel()
{
    int i = blockIdx.x * blockDim.x + threadIdx.x;
    if (i < N_NODES) { g_deg[i] = 0; g_fill[i] = 0; }
}

__global__ __launch_bounds__(256)
void count_kernel(const int* __restrict__ edge_row)
{
    int e = blockIdx.x * blockDim.x + threadIdx.x;
    if (e < N_EDGES) atomicAdd(&g_deg[edge_row[e]], 1);
}

__global__ __launch_bounds__(1024)
void scan_kernel()
{
    __shared__ int partial[1024];
    const int t = threadIdx.x;
    const int CHUNK = (N_NODES + 1023) / 1024;
    const int base = t * CHUNK;

    int s = 0;
    for (int i = 0; i < CHUNK; i++) {
        int idx = base + i;
        if (idx < N_NODES) s += g_deg[idx];
    }
    partial[t] = s;
    __syncthreads();

    for (int off = 1; off < 1024; off <<= 1) {
        int v = (t >= off) ? partial[t - off] : 0;
        __syncthreads();
        partial[t] += v;
        __syncthreads();
    }

    int run = (t == 0) ? 0 : partial[t - 1];
    for (int i = 0; i < CHUNK; i++) {
        int idx = base + i;
        if (idx < N_NODES) { g_rowptr[idx] = run; run += g_deg[idx]; }
    }
    if (t == 1023) g_rowptr[N_NODES] = partial[1023];
}

__global__ __launch_bounds__(256)
void fill_kernel(const int*   __restrict__ edge_row,
                 const int*   __restrict__ edge_col,
                 const float* __restrict__ edge_vals)
{
    int e = blockIdx.x * blockDim.x + threadIdx.x;
    if (e >= N_EDGES) return;
    const int r = edge_row[e];
    const int p = g_rowptr[r] + atomicAdd(&g_fill[r], 1);
    g_epack[p] = make_int2(edge_col[e], __float_as_int(edge_vals[e]));
}

// ---------------------------------------------------------------------------
// SpMM chunk: out[:, co:co+128] = relu(A @ xwh[:, co:co+128] + bias)
// One warp per row. Edge metadata fetched coalesced (lane-parallel) then
// broadcast via shfl; 8 gathers in flight; fp32 accumulate.
// ---------------------------------------------------------------------------
__device__ __forceinline__ void fma_half4(float4& acc, float v, uint2 m)
{
    const __half2 h01 = *reinterpret_cast<const __half2*>(&m.x);
    const __half2 h23 = *reinterpret_cast<const __half2*>(&m.y);
    const float2 f01 = __half22float2(h01);
    const float2 f23 = __half22float2(h23);
    acc.x = fmaf(v, f01.x, acc.x);
    acc.y = fmaf(v, f01.y, acc.y);
    acc.z = fmaf(v, f23.x, acc.z);
    acc.w = fmaf(v, f23.y, acc.w);
}

__global__ __launch_bounds__(256)
void spmm_chunk_kernel(const float* __restrict__ bias,
                       float*       __restrict__ out,
                       int co)
{
    const int row  = (blockIdx.x * blockDim.x + threadIdx.x) >> 5;
    const int lane = threadIdx.x & 31;
    if (row >= N_NODES) return;

    const int s = g_rowptr[row];
    const int e = g_rowptr[row + 1];
    const int c = co + lane * 4;

    float4 acc = make_float4(0.f, 0.f, 0.f, 0.f);

    int base = s;
    while (base < e) {
        const int navail = min(32, e - base);

        // coalesced edge fetch: lane i holds edge base+i
        int2 pe = make_int2(0, 0);
        if (lane < navail) pe = __ldg(&g_epack[base + lane]);

        int j = 0;
        for (; j + 7 < navail; j += 8) {
            int   col[8];
            float val[8];
            uint2 m[8];
            #pragma unroll
            for (int q = 0; q < 8; q++) {
                col[q] = __shfl_sync(0xffffffffu, pe.x, j + q);
                val[q] = __int_as_float(__shfl_sync(0xffffffffu, pe.y, j + q));
            }
            #pragma unroll
            for (int q = 0; q < 8; q++)
                m[q] = __ldg(reinterpret_cast<const uint2*>(&g_xwh[(size_t)col[q] * D_OUT + c]));
            #pragma unroll
            for (int q = 0; q < 8; q++)
                fma_half4(acc, val[q], m[q]);
        }
        // remainder (0..7 edges)
        for (; j < navail; j++) {
            const int   col = __shfl_sync(0xffffffffu, pe.x, j);
            const float val = __int_as_float(__shfl_sync(0xffffffffu, pe.y, j));
            const uint2 m = __ldg(reinterpret_cast<const uint2*>(&g_xwh[(size_t)col * D_OUT + c]));
            fma_half4(acc, val, m);
        }
        base += navail;
    }

    const float4 b = *reinterpret_cast<const float4*>(&bias[c]);
    acc.x = fmaxf(acc.x + b.x, 0.f);
    acc.y = fmaxf(acc.y + b.y, 0.f);
    acc.z = fmaxf(acc.z + b.z, 0.f);
    acc.w = fmaxf(acc.w + b.w, 0.f);

    *reinterpret_cast<float4*>(&out[(size_t)row * D_OUT + c]) = acc;
}

// ---------------------------------------------------------------------------
// Launch: 3-stream schedule.
//   side : cvt x/W, G0 (ev0), G1 (ev1)
//   s2   : wait ev0 + ev_build -> S0 (ev_s0)
//   main : build (ev_build), wait ev1 -> S1, wait ev_s0 (join)
// ---------------------------------------------------------------------------
static cudaStream_t g_side = nullptr;
static cudaStream_t g_s2   = nullptr;
static cudaEvent_t  g_fork = nullptr;
static cudaEvent_t  g_ev[N_CHUNKS] = {nullptr, nullptr};
static cudaEvent_t  g_ev_build = nullptr;
static cudaEvent_t  g_ev_s0    = nullptr;

extern "C" void kernel_launch(void* const* d_in, const int* in_sizes, int n_in,
                              void* d_out, int out_size)
{
    const float* x         = (const float*)d_in[0];
    const int*   edge_row  = (const int*)  d_in[1];
    const int*   edge_col  = (const int*)  d_in[2];
    const float* edge_vals = (const float*)d_in[3];
    const float* weight    = (const float*)d_in[4];
    const float* bias      = (const float*)d_in[5];
    float* out = (float*)d_out;

    if (g_side == nullptr) {
        cudaStreamCreateWithFlags(&g_side, cudaStreamNonBlocking);
        cudaStreamCreateWithFlags(&g_s2,   cudaStreamNonBlocking);
        cudaEventCreateWithFlags(&g_fork, cudaEventDisableTiming);
        for (int k = 0; k < N_CHUNKS; k++)
            cudaEventCreateWithFlags(&g_ev[k], cudaEventDisableTiming);
        cudaEventCreateWithFlags(&g_ev_build, cudaEventDisableTiming);
        cudaEventCreateWithFlags(&g_ev_s0,    cudaEventDisableTiming);
    }

    // Fork
    cudaEventRecord(g_fork, 0);
    cudaStreamWaitEvent(g_side, g_fork, 0);
    cudaStreamWaitEvent(g_s2,   g_fork, 0);

    // Side: fp16 conversion + GEMM chunks
    {
        const size_t nx4 = (size_t)PAD_NODES * D_IN / 4;
        convert_x_kernel<<<(int)((nx4 + 255) / 256), 256, 0, g_side>>>(x);
        const size_t nw4 = (size_t)D_IN * D_OUT / 4;
        convert_w_kernel<<<(int)((nw4 + 255) / 256), 256, 0, g_side>>>(weight);

        const int gemm_blocks = PAD_NODES / BLK_M;
        for (int k = 0; k < N_CHUNKS; k++) {
            wmma_gemm_kernel<<<gemm_blocks, 256, 0, g_side>>>(k * CHUNK_COLS);
            cudaEventRecord(g_ev[k], g_side);
        }
    }

    // Main: CSR build
    zero_counts_kernel<<<(N_NODES + 255) / 256, 256>>>();
    count_kernel<<<(N_EDGES + 255) / 256, 256>>>(edge_row);
    scan_kernel<<<1, 1024>>>();
    fill_kernel<<<(N_EDGES + 255) / 256, 256>>>(edge_row, edge_col, edge_vals);
    cudaEventRecord(g_ev_build, 0);

    const int spmm_blocks = (N_NODES * 32 + 255) / 256;

    // s2: S0 after G0 + build
    cudaStreamWaitEvent(g_s2, g_ev[0], 0);
    cudaStreamWaitEvent(g_s2, g_ev_build, 0);
    spmm_chunk_kernel<<<spmm_blocks, 256, 0, g_s2>>>(bias, out, 0);
    cudaEventRecord(g_ev_s0, g_s2);

    // main: S1 after G1 (build already done on main)
    cudaStreamWaitEvent(0, g_ev[1], 0);
    spmm_chunk_kernel<<<spmm_blocks, 256>>>(bias, out, CHUNK_COLS);

    // join
    cudaStreamWaitEvent(0, g_ev_s0, 0);
}

// round 10
// speedup vs baseline: 1.8234x; 1.1541x over previous
#include <cuda_runtime.h>
#include <cuda_fp16.h>
#include <mma.h>
#include <cstdint>

using namespace nvcuda;

#define N_NODES   50000
#define PAD_NODES 50048        // multiple of 128 (GEMM M-tile)
#define N_EDGES   800000
#define D_IN      256
#define D_OUT     256

// ---------------- static device scratch (no allocations) -------------------
__device__ __align__(16) __half g_wh [(size_t)D_IN * D_OUT];       // W in fp16
__device__ __align__(16) __half g_xwh[(size_t)PAD_NODES * D_OUT];  // xw in fp16
__device__ int  g_deg[N_NODES];
__device__ int  g_fill[N_NODES];
__device__ int  g_rowptr[N_NODES + 1];
__device__ int2 g_epack[N_EDGES];                                   // {col, bitcast(val)}

// ---------------------------------------------------------------------------
// W fp32 -> fp16
// ---------------------------------------------------------------------------
__global__ __launch_bounds__(256)
void convert_w_kernel(const float* __restrict__ W)
{
    const size_t idx = (size_t)blockIdx.x * blockDim.x + threadIdx.x;
    const size_t i4  = idx * 4;
    if (i4 >= (size_t)D_IN * D_OUT) return;
    const float4 v = *reinterpret_cast<const float4*>(&W[i4]);
    const __half2 h01 = __floats2half2_rn(v.x, v.y);
    const __half2 h23 = __floats2half2_rn(v.z, v.w);
    uint2 u;
    u.x = *reinterpret_cast<const unsigned int*>(&h01);
    u.y = *reinterpret_cast<const unsigned int*>(&h23);
    *reinterpret_cast<uint2*>(&g_wh[i4]) = u;
}

// ---------------------------------------------------------------------------
// Monolithic HMMA GEMM: xwh = (half)(x @ W), all 256 cols.
// Grid (PAD_NODES/128, 2). Block 128M x 128N, BK=32, 8 warps (4x2),
// warp tile 32x64. A converted fp32->fp16 in-kernel while staging to smem.
// ---------------------------------------------------------------------------
#define BLK_M 128
#define BLK_N 128
#define BLK_K 32
#define A_LD  (BLK_K + 8)     // 40 halves (80B rows, 16B-aligned)
#define B_LD  (BLK_N + 8)     // 136 halves

__global__ __launch_bounds__(256)
void wmma_gemm_kernel(const float* __restrict__ x)
{
    __shared__ __half As[2][BLK_M * A_LD];
    __shared__ __half Bs[2][BLK_K * B_LD];
    __shared__ float  ebuf[8][16 * 16];

    const int t    = threadIdx.x;
    const int warp = t >> 5;
    const int lane = t & 31;
    const int wm   = warp & 3;                  // 0..3 (M)
    const int wn   = warp >> 2;                 // 0..1 (N)
    const int row0 = blockIdx.x * BLK_M;
    const int col0 = blockIdx.y * BLK_N;

    wmma::fragment<wmma::accumulator, 16, 16, 16, float> acc[2][4];
    #pragma unroll
    for (int i = 0; i < 2; i++)
        #pragma unroll
        for (int j = 0; j < 4; j++)
            wmma::fill_fragment(acc[i][j], 0.0f);

    // A: thread t covers row = t>>1, halves [(t&1)*16, +16) -- 4 float4 loads
    const int a_row = t >> 1;
    const int a_c16 = (t & 1) * 16;
    const int gm_a  = row0 + a_row;
    const bool a_ok = (gm_a < N_NODES);
    const float* a_ptr = x + (size_t)gm_a * D_IN + a_c16;

    // B: 32 rows x 128 halves = 512 uint4; 2 per thread
    auto load_a_g = [&](int k0, float4* r) {
        #pragma unroll
        for (int q = 0; q < 4; q++)
            r[q] = a_ok ? *reinterpret_cast<const float4*>(a_ptr + k0 + q * 4)
                        : make_float4(0.f, 0.f, 0.f, 0.f);
    };
    auto load_b_g = [&](int k0, uint4* r) {
        #pragma unroll
        for (int q = 0; q < 2; q++) {
            const int idx = t + q * 256;
            const int row = idx >> 4;
            const int c8  = (idx & 15) * 8;
            r[q] = *reinterpret_cast<const uint4*>(
                &g_wh[(size_t)(k0 + row) * D_OUT + col0 + c8]);
        }
    };
    auto store_a_s = [&](int buf, const float4* r) {
        union { __half h[16]; uint4 u[2]; } pk;
        #pragma unroll
        for (int q = 0; q < 4; q++) {
            const __half2 h01 = __floats2half2_rn(r[q].x, r[q].y);
            const __half2 h23 = __floats2half2_rn(r[q].z, r[q].w);
            pk.h[q * 4 + 0] = __low2half(h01);
            pk.h[q * 4 + 1] = __high2half(h01);
            pk.h[q * 4 + 2] = __low2half(h23);
            pk.h[q * 4 + 3] = __high2half(h23);
        }
        uint4* dst = reinterpret_cast<uint4*>(&As[buf][a_row * A_LD + a_c16]);
        dst[0] = pk.u[0];
        dst[1] = pk.u[1];
    };
    auto store_b_s = [&](int buf, const uint4* r) {
        #pragma unroll
        for (int q = 0; q < 2; q++) {
            const int idx = t + q * 256;
            const int row = idx >> 4;
            const int c8  = (idx & 15) * 8;
            *reinterpret_cast<uint4*>(&Bs[buf][row * B_LD + c8]) = r[q];
        }
    };

    float4 ra[4];
    uint4  rb[2];
    load_a_g(0, ra);
    load_b_g(0, rb);
    store_a_s(0, ra);
    store_b_s(0, rb);
    __syncthreads();

    const int NSTEP = D_IN / BLK_K;   // 8
    int buf = 0;

    for (int s = 0; s < NSTEP; s++) {
        if (s + 1 < NSTEP) {
            load_a_g((s + 1) * BLK_K, ra);
            load_b_g((s + 1) * BLK_K, rb);
        }

        #pragma unroll
        for (int kk = 0; kk < 2; kk++) {
            wmma::fragment<wmma::matrix_a, 16, 16, 16, __half, wmma::row_major> a0, a1;
            wmma::load_matrix_sync(a0, &As[buf][(wm * 32 +  0) * A_LD + kk * 16], A_LD);
            wmma::load_matrix_sync(a1, &As[buf][(wm * 32 + 16) * A_LD + kk * 16], A_LD);
            #pragma unroll
            for (int j = 0; j < 4; j++) {
                wmma::fragment<wmma::matrix_b, 16, 16, 16, __half, wmma::row_major> b;
                wmma::load_matrix_sync(b, &Bs[buf][(kk * 16) * B_LD + wn * 64 + j * 16], B_LD);
                wmma::mma_sync(acc[0][j], a0, b, acc[0][j]);
                wmma::mma_sync(acc[1][j], a1, b, acc[1][j]);
            }
        }

        if (s + 1 < NSTEP) {
            const int nb = buf ^ 1;
            store_a_s(nb, ra);
            store_b_s(nb, rb);
            __syncthreads();
            buf = nb;
        }
    }

    // epilogue: frag -> smem fp32 -> fp16 vector store
    const int r  = lane >> 1;
    const int cc = (lane & 1) * 8;
    const int c0 = col0 + wn * 64;

    #pragma unroll
    for (int i = 0; i < 2; i++) {
        #pragma unroll
        for (int j = 0; j < 4; j++) {
            wmma::store_matrix_sync(ebuf[warp], acc[i][j], 16, wmma::mem_row_major);
            __syncwarp();
            const int grow = row0 + wm * 32 + i * 16 + r;
            if (grow < N_NODES) {
                union { __half h[8]; uint4 u; } pk;
                #pragma unroll
                for (int q = 0; q < 8; q++)
                    pk.h[q] = __float2half(ebuf[warp][r * 16 + cc + q]);
                *reinterpret_cast<uint4*>(&g_xwh[(size_t)grow * D_OUT + c0 + j * 16 + cc]) = pk.u;
            }
            __syncwarp();
        }
    }
}

// ---------------------------------------------------------------------------
// CSR construction
// ---------------------------------------------------------------------------
__global__ __launch_bounds__(256)
void zero_counts_kernel()
{
    int i = blockIdx.x * blockDim.x + threadIdx.x;
    if (i < N_NODES) { g_deg[i] = 0; g_fill[i] = 0; }
}

__global__ __launch_bounds__(256)
void count_kernel(const int* __restrict__ edge_row)
{
    int e = blockIdx.x * blockDim.x + threadIdx.x;
    if (e < N_EDGES) atomicAdd(&g_deg[edge_row[e]], 1);
}

__global__ __launch_bounds__(1024)
void scan_kernel()
{
    __shared__ int partial[1024];
    const int t = threadIdx.x;
    const int CHUNK = (N_NODES + 1023) / 1024;
    const int base = t * CHUNK;

    int s = 0;
    for (int i = 0; i < CHUNK; i++) {
        int idx = base + i;
        if (idx < N_NODES) s += g_deg[idx];
    }
    partial[t] = s;
    __syncthreads();

    for (int off = 1; off < 1024; off <<= 1) {
        int v = (t >= off) ? partial[t - off] : 0;
        __syncthreads();
        partial[t] += v;
        __syncthreads();
    }

    int run = (t == 0) ? 0 : partial[t - 1];
    for (int i = 0; i < CHUNK; i++) {
        int idx = base + i;
        if (idx < N_NODES) { g_rowptr[idx] = run; run += g_deg[idx]; }
    }
    if (t == 1023) g_rowptr[N_NODES] = partial[1023];
}

__global__ __launch_bounds__(256)
void fill_kernel(const int*   __restrict__ edge_row,
                 const int*   __restrict__ edge_col,
                 const float* __restrict__ edge_vals)
{
    int e = blockIdx.x * blockDim.x + threadIdx.x;
    if (e >= N_EDGES) return;
    const int r = edge_row[e];
    const int p = g_rowptr[r] + atomicAdd(&g_fill[r], 1);
    g_epack[p] = make_int2(edge_col[e], __float_as_int(edge_vals[e]));
}

// ---------------------------------------------------------------------------
// Monolithic SpMM: out = relu(A @ xwh + bias), all 256 cols.
// One warp per row; lane owns 8 halves (uint4, one 512B warp gather per edge);
// 4-edge unroll (16 L2 lines in flight); coalesced epack fetch + shfl bcast.
// ---------------------------------------------------------------------------
__device__ __forceinline__ void fma_half8(float* acc, float v, uint4 m)
{
    const __half2* h = reinterpret_cast<const __half2*>(&m);
    #pragma unroll
    for (int q = 0; q < 4; q++) {
        const float2 f = __half22float2(h[q]);
        acc[q * 2 + 0] = fmaf(v, f.x, acc[q * 2 + 0]);
        acc[q * 2 + 1] = fmaf(v, f.y, acc[q * 2 + 1]);
    }
}

__global__ __launch_bounds__(256)
void spmm_kernel(const float* __restrict__ bias,
                 float*       __restrict__ out)
{
    const int row  = (blockIdx.x * blockDim.x + threadIdx.x) >> 5;
    const int lane = threadIdx.x & 31;
    if (row >= N_NODES) return;

    const int s = g_rowptr[row];
    const int e = g_rowptr[row + 1];
    const int c = lane * 8;                       // halves index within 256

    float acc[8];
    #pragma unroll
    for (int q = 0; q < 8; q++) acc[q] = 0.f;

    int base = s;
    while (base < e) {
        const int navail = min(32, e - base);

        int2 pe = make_int2(0, 0);
        if (lane < navail) pe = __ldg(&g_epack[base + lane]);

        int j = 0;
        for (; j + 3 < navail; j += 4) {
            int   col[4];
            float val[4];
            uint4 m[4];
            #pragma unroll
            for (int q = 0; q < 4; q++) {
                col[q] = __shfl_sync(0xffffffffu, pe.x, j + q);
                val[q] = __int_as_float(__shfl_sync(0xffffffffu, pe.y, j + q));
            }
            #pragma unroll
            for (int q = 0; q < 4; q++)
                m[q] = __ldg(reinterpret_cast<const uint4*>(&g_xwh[(size_t)col[q] * D_OUT + c]));
            #pragma unroll
            for (int q = 0; q < 4; q++)
                fma_half8(acc, val[q], m[q]);
        }
        for (; j < navail; j++) {
            const int   col = __shfl_sync(0xffffffffu, pe.x, j);
            const float val = __int_as_float(__shfl_sync(0xffffffffu, pe.y, j));
            const uint4 m = __ldg(reinterpret_cast<const uint4*>(&g_xwh[(size_t)col * D_OUT + c]));
            fma_half8(acc, val, m);
        }
        base += navail;
    }

    const float4 b0 = *reinterpret_cast<const float4*>(&bias[c]);
    const float4 b1 = *reinterpret_cast<const float4*>(&bias[c + 4]);
    float4 o0, o1;
    o0.x = fmaxf(acc[0] + b0.x, 0.f);
    o0.y = fmaxf(acc[1] + b0.y, 0.f);
    o0.z = fmaxf(acc[2] + b0.z, 0.f);
    o0.w = fmaxf(acc[3] + b0.w, 0.f);
    o1.x = fmaxf(acc[4] + b1.x, 0.f);
    o1.y = fmaxf(acc[5] + b1.y, 0.f);
    o1.z = fmaxf(acc[6] + b1.z, 0.f);
    o1.w = fmaxf(acc[7] + b1.w, 0.f);

    float* dst = &out[(size_t)row * D_OUT + c];
    *reinterpret_cast<float4*>(dst)     = o0;
    *reinterpret_cast<float4*>(dst + 4) = o1;
}

// ---------------------------------------------------------------------------
// Launch:
//   side : cvt W -> monolithic GEMM (ev_g)
//   main : CSR build ; wait ev_g ; monolithic SpMM
// ---------------------------------------------------------------------------
static cudaStream_t g_side = nullptr;
static cudaEvent_t  g_fork = nullptr;
static cudaEvent_t  g_evg  = nullptr;

extern "C" void kernel_launch(void* const* d_in, const int* in_sizes, int n_in,
                              void* d_out, int out_size)
{
    const float* x         = (const float*)d_in[0];
    const int*   edge_row  = (const int*)  d_in[1];
    const int*   edge_col  = (const int*)  d_in[2];
    const float* edge_vals = (const float*)d_in[3];
    const float* weight    = (const float*)d_in[4];
    const float* bias      = (const float*)d_in[5];
    float* out = (float*)d_out;

    if (g_side == nullptr) {
        cudaStreamCreateWithFlags(&g_side, cudaStreamNonBlocking);
        cudaEventCreateWithFlags(&g_fork, cudaEventDisableTiming);
        cudaEventCreateWithFlags(&g_evg,  cudaEventDisableTiming);
    }

    // Fork side stream
    cudaEventRecord(g_fork, 0);
    cudaStreamWaitEvent(g_side, g_fork, 0);

    // Side: W conversion + monolithic GEMM (x converted in-kernel)
    {
        const size_t nw4 = (size_t)D_IN * D_OUT / 4;
        convert_w_kernel<<<(int)((nw4 + 255) / 256), 256, 0, g_side>>>(weight);
        dim3 ggrid(PAD_NODES / BLK_M, D_OUT / BLK_N);
        wmma_gemm_kernel<<<ggrid, 256, 0, g_side>>>(x);
        cudaEventRecord(g_evg, g_side);
    }

    // Main: CSR build (overlaps GEMM)
    zero_counts_kernel<<<(N_NODES + 255) / 256, 256>>>();
    count_kernel<<<(N_EDGES + 255) / 256, 256>>>(edge_row);
    scan_kernel<<<1, 1024>>>();
    fill_kernel<<<(N_EDGES + 255) / 256, 256>>>(edge_row, edge_col, edge_vals);

    // Main: SpMM after GEMM
    cudaStreamWaitEvent(0, g_evg, 0);
    const int spmm_blocks = (N_NODES * 32 + 255) / 256;
    spmm_kernel<<<spmm_blocks, 256>>>(bias, out);
}

// round 11
// speedup vs baseline: 1.8556x; 1.0177x over previous
#include <cuda_runtime.h>
#include <cuda_fp16.h>
#include <mma.h>
#include <cstdint>

using namespace nvcuda;

#define N_NODES   50000
#define PAD_NODES 50048        // multiple of 128 (GEMM M-tile)
#define N_EDGES   800000
#define D_IN      256
#define D_OUT     256

// ---------------- static device scratch (no allocations) -------------------
__device__ __align__(16) __half g_wh [(size_t)D_IN * D_OUT];       // W in fp16
__device__ __align__(16) __half g_xwh[(size_t)PAD_NODES * D_OUT];  // xw in fp16
__device__ int  g_deg[N_NODES];
__device__ int  g_fill[N_NODES];
__device__ int  g_rowptr[N_NODES + 1];
__device__ int2 g_epack[N_EDGES];                                   // {col, bitcast(val)}

// ---------------------------------------------------------------------------
// W fp32 -> fp16
// ---------------------------------------------------------------------------
__global__ __launch_bounds__(256)
void convert_w_kernel(const float* __restrict__ W)
{
    const size_t idx = (size_t)blockIdx.x * blockDim.x + threadIdx.x;
    const size_t i4  = idx * 4;
    if (i4 >= (size_t)D_IN * D_OUT) return;
    const float4 v = *reinterpret_cast<const float4*>(&W[i4]);
    const __half2 h01 = __floats2half2_rn(v.x, v.y);
    const __half2 h23 = __floats2half2_rn(v.z, v.w);
    uint2 u;
    u.x = *reinterpret_cast<const unsigned int*>(&h01);
    u.y = *reinterpret_cast<const unsigned int*>(&h23);
    *reinterpret_cast<uint2*>(&g_wh[i4]) = u;
}

// ---------------------------------------------------------------------------
// Monolithic HMMA GEMM: xwh = (half)(x @ W), all 256 cols — unchanged (R9).
// ---------------------------------------------------------------------------
#define BLK_M 128
#define BLK_N 128
#define BLK_K 32
#define A_LD  (BLK_K + 8)
#define B_LD  (BLK_N + 8)

__global__ __launch_bounds__(256)
void wmma_gemm_kernel(const float* __restrict__ x)
{
    __shared__ __half As[2][BLK_M * A_LD];
    __shared__ __half Bs[2][BLK_K * B_LD];
    __shared__ float  ebuf[8][16 * 16];

    const int t    = threadIdx.x;
    const int warp = t >> 5;
    const int lane = t & 31;
    const int wm   = warp & 3;
    const int wn   = warp >> 2;
    const int row0 = blockIdx.x * BLK_M;
    const int col0 = blockIdx.y * BLK_N;

    wmma::fragment<wmma::accumulator, 16, 16, 16, float> acc[2][4];
    #pragma unroll
    for (int i = 0; i < 2; i++)
        #pragma unroll
        for (int j = 0; j < 4; j++)
            wmma::fill_fragment(acc[i][j], 0.0f);

    const int a_row = t >> 1;
    const int a_c16 = (t & 1) * 16;
    const int gm_a  = row0 + a_row;
    const bool a_ok = (gm_a < N_NODES);
    const float* a_ptr = x + (size_t)gm_a * D_IN + a_c16;

    auto load_a_g = [&](int k0, float4* r) {
        #pragma unroll
        for (int q = 0; q < 4; q++)
            r[q] = a_ok ? *reinterpret_cast<const float4*>(a_ptr + k0 + q * 4)
                        : make_float4(0.f, 0.f, 0.f, 0.f);
    };
    auto load_b_g = [&](int k0, uint4* r) {
        #pragma unroll
        for (int q = 0; q < 2; q++) {
            const int idx = t + q * 256;
            const int row = idx >> 4;
            const int c8  = (idx & 15) * 8;
            r[q] = *reinterpret_cast<const uint4*>(
                &g_wh[(size_t)(k0 + row) * D_OUT + col0 + c8]);
        }
    };
    auto store_a_s = [&](int buf, const float4* r) {
        union { __half h[16]; uint4 u[2]; } pk;
        #pragma unroll
        for (int q = 0; q < 4; q++) {
            const __half2 h01 = __floats2half2_rn(r[q].x, r[q].y);
            const __half2 h23 = __floats2half2_rn(r[q].z, r[q].w);
            pk.h[q * 4 + 0] = __low2half(h01);
            pk.h[q * 4 + 1] = __high2half(h01);
            pk.h[q * 4 + 2] = __low2half(h23);
            pk.h[q * 4 + 3] = __high2half(h23);
        }
        uint4* dst = reinterpret_cast<uint4*>(&As[buf][a_row * A_LD + a_c16]);
        dst[0] = pk.u[0];
        dst[1] = pk.u[1];
    };
    auto store_b_s = [&](int buf, const uint4* r) {
        #pragma unroll
        for (int q = 0; q < 2; q++) {
            const int idx = t + q * 256;
            const int row = idx >> 4;
            const int c8  = (idx & 15) * 8;
            *reinterpret_cast<uint4*>(&Bs[buf][row * B_LD + c8]) = r[q];
        }
    };

    float4 ra[4];
    uint4  rb[2];
    load_a_g(0, ra);
    load_b_g(0, rb);
    store_a_s(0, ra);
    store_b_s(0, rb);
    __syncthreads();

    const int NSTEP = D_IN / BLK_K;
    int buf = 0;

    for (int s = 0; s < NSTEP; s++) {
        if (s + 1 < NSTEP) {
            load_a_g((s + 1) * BLK_K, ra);
            load_b_g((s + 1) * BLK_K, rb);
        }

        #pragma unroll
        for (int kk = 0; kk < 2; kk++) {
            wmma::fragment<wmma::matrix_a, 16, 16, 16, __half, wmma::row_major> a0, a1;
            wmma::load_matrix_sync(a0, &As[buf][(wm * 32 +  0) * A_LD + kk * 16], A_LD);
            wmma::load_matrix_sync(a1, &As[buf][(wm * 32 + 16) * A_LD + kk * 16], A_LD);
            #pragma unroll
            for (int j = 0; j < 4; j++) {
                wmma::fragment<wmma::matrix_b, 16, 16, 16, __half, wmma::row_major> b;
                wmma::load_matrix_sync(b, &Bs[buf][(kk * 16) * B_LD + wn * 64 + j * 16], B_LD);
                wmma::mma_sync(acc[0][j], a0, b, acc[0][j]);
                wmma::mma_sync(acc[1][j], a1, b, acc[1][j]);
            }
        }

        if (s + 1 < NSTEP) {
            const int nb = buf ^ 1;
            store_a_s(nb, ra);
            store_b_s(nb, rb);
            __syncthreads();
            buf = nb;
        }
    }

    const int r  = lane >> 1;
    const int cc = (lane & 1) * 8;
    const int c0 = col0 + wn * 64;

    #pragma unroll
    for (int i = 0; i < 2; i++) {
        #pragma unroll
        for (int j = 0; j < 4; j++) {
            wmma::store_matrix_sync(ebuf[warp], acc[i][j], 16, wmma::mem_row_major);
            __syncwarp();
            const int grow = row0 + wm * 32 + i * 16 + r;
            if (grow < N_NODES) {
                union { __half h[8]; uint4 u; } pk;
                #pragma unroll
                for (int q = 0; q < 8; q++)
                    pk.h[q] = __float2half(ebuf[warp][r * 16 + cc + q]);
                *reinterpret_cast<uint4*>(&g_xwh[(size_t)grow * D_OUT + c0 + j * 16 + cc]) = pk.u;
            }
            __syncwarp();
        }
    }
}

// ---------------------------------------------------------------------------
// CSR construction (count/fill vectorized x4)
// ---------------------------------------------------------------------------
__global__ __launch_bounds__(256)
void zero_counts_kernel()
{
    int i = blockIdx.x * blockDim.x + threadIdx.x;
    if (i < N_NODES) { g_deg[i] = 0; g_fill[i] = 0; }
}

__global__ __launch_bounds__(256)
void count_kernel(const int* __restrict__ edge_row)
{
    const int e4 = (blockIdx.x * blockDim.x + threadIdx.x) * 4;
    if (e4 + 3 < N_EDGES) {
        const int4 r = *reinterpret_cast<const int4*>(&edge_row[e4]);
        atomicAdd(&g_deg[r.x], 1);
        atomicAdd(&g_deg[r.y], 1);
        atomicAdd(&g_deg[r.z], 1);
        atomicAdd(&g_deg[r.w], 1);
    } else {
        for (int e = e4; e < N_EDGES; e++)
            atomicAdd(&g_deg[edge_row[e]], 1);
    }
}

__global__ __launch_bounds__(1024)
void scan_kernel()
{
    __shared__ int partial[1024];
    const int t = threadIdx.x;
    const int CHUNK = (N_NODES + 1023) / 1024;
    const int base = t * CHUNK;

    int s = 0;
    for (int i = 0; i < CHUNK; i++) {
        int idx = base + i;
        if (idx < N_NODES) s += g_deg[idx];
    }
    partial[t] = s;
    __syncthreads();

    for (int off = 1; off < 1024; off <<= 1) {
        int v = (t >= off) ? partial[t - off] : 0;
        __syncthreads();
        partial[t] += v;
        __syncthreads();
    }

    int run = (t == 0) ? 0 : partial[t - 1];
    for (int i = 0; i < CHUNK; i++) {
        int idx = base + i;
        if (idx < N_NODES) { g_rowptr[idx] = run; run += g_deg[idx]; }
    }
    if (t == 1023) g_rowptr[N_NODES] = partial[1023];
}

__global__ __launch_bounds__(256)
void fill_kernel(const int*   __restrict__ edge_row,
                 const int*   __restrict__ edge_col,
                 const float* __restrict__ edge_vals)
{
    const int e4 = (blockIdx.x * blockDim.x + threadIdx.x) * 4;
    if (e4 + 3 < N_EDGES) {
        const int4   r = *reinterpret_cast<const int4*>(&edge_row[e4]);
        const int4   c = *reinterpret_cast<const int4*>(&edge_col[e4]);
        const float4 v = *reinterpret_cast<const float4*>(&edge_vals[e4]);
        int p;
        p = g_rowptr[r.x] + atomicAdd(&g_fill[r.x], 1);
        g_epack[p] = make_int2(c.x, __float_as_int(v.x));
        p = g_rowptr[r.y] + atomicAdd(&g_fill[r.y], 1);
        g_epack[p] = make_int2(c.y, __float_as_int(v.y));
        p = g_rowptr[r.z] + atomicAdd(&g_fill[r.z], 1);
        g_epack[p] = make_int2(c.z, __float_as_int(v.z));
        p = g_rowptr[r.w] + atomicAdd(&g_fill[r.w], 1);
        g_epack[p] = make_int2(c.w, __float_as_int(v.w));
    } else {
        for (int e = e4; e < N_EDGES; e++) {
            const int rr = edge_row[e];
            const int p = g_rowptr[rr] + atomicAdd(&g_fill[rr], 1);
            g_epack[p] = make_int2(edge_col[e], __float_as_int(edge_vals[e]));
        }
    }
}

// ---------------------------------------------------------------------------
// Monolithic SpMM: out = relu(A @ xwh + bias)
// One warp per row; lane owns 8 halves (one uint4 = 512B warp gather/edge);
// 8-edge unroll => 32 L2 lines in flight per warp.
// ---------------------------------------------------------------------------
__device__ __forceinline__ void fma_half8(float* acc, float v, uint4 m)
{
    const __half2* h = reinterpret_cast<const __half2*>(&m);
    #pragma unroll
    for (int q = 0; q < 4; q++) {
        const float2 f = __half22float2(h[q]);
        acc[q * 2 + 0] = fmaf(v, f.x, acc[q * 2 + 0]);
        acc[q * 2 + 1] = fmaf(v, f.y, acc[q * 2 + 1]);
    }
}

__global__ __launch_bounds__(256)
void spmm_kernel(const float* __restrict__ bias,
                 float*       __restrict__ out)
{
    const int row  = (blockIdx.x * blockDim.x + threadIdx.x) >> 5;
    const int lane = threadIdx.x & 31;
    if (row >= N_NODES) return;

    const int s = g_rowptr[row];
    const int e = g_rowptr[row + 1];
    const int c = lane * 8;

    float acc[8];
    #pragma unroll
    for (int q = 0; q < 8; q++) acc[q] = 0.f;

    int base = s;
    while (base < e) {
        const int navail = min(32, e - base);

        int2 pe = make_int2(0, 0);
        if (lane < navail) pe = __ldg(&g_epack[base + lane]);

        int j = 0;
        for (; j + 7 < navail; j += 8) {
            int   col[8];
            float val[8];
            uint4 m[8];
            #pragma unroll
            for (int q = 0; q < 8; q++) {
                col[q] = __shfl_sync(0xffffffffu, pe.x, j + q);
                val[q] = __int_as_float(__shfl_sync(0xffffffffu, pe.y, j + q));
            }
            #pragma unroll
            for (int q = 0; q < 8; q++)
                m[q] = __ldg(reinterpret_cast<const uint4*>(&g_xwh[(size_t)col[q] * D_OUT + c]));
            #pragma unroll
            for (int q = 0; q < 8; q++)
                fma_half8(acc, val[q], m[q]);
        }
        if (j + 3 < navail) {
            int   col[4];
            float val[4];
            uint4 m[4];
            #pragma unroll
            for (int q = 0; q < 4; q++) {
                col[q] = __shfl_sync(0xffffffffu, pe.x, j + q);
                val[q] = __int_as_float(__shfl_sync(0xffffffffu, pe.y, j + q));
            }
            #pragma unroll
            for (int q = 0; q < 4; q++)
                m[q] = __ldg(reinterpret_cast<const uint4*>(&g_xwh[(size_t)col[q] * D_OUT + c]));
            #pragma unroll
            for (int q = 0; q < 4; q++)
                fma_half8(acc, val[q], m[q]);
            j += 4;
        }
        for (; j < navail; j++) {
            const int   col = __shfl_sync(0xffffffffu, pe.x, j);
            const float val = __int_as_float(__shfl_sync(0xffffffffu, pe.y, j));
            const uint4 m = __ldg(reinterpret_cast<const uint4*>(&g_xwh[(size_t)col * D_OUT + c]));
            fma_half8(acc, val, m);
        }
        base += navail;
    }

    const float4 b0 = *reinterpret_cast<const float4*>(&bias[c]);
    const float4 b1 = *reinterpret_cast<const float4*>(&bias[c + 4]);
    float4 o0, o1;
    o0.x = fmaxf(acc[0] + b0.x, 0.f);
    o0.y = fmaxf(acc[1] + b0.y, 0.f);
    o0.z = fmaxf(acc[2] + b0.z, 0.f);
    o0.w = fmaxf(acc[3] + b0.w, 0.f);
    o1.x = fmaxf(acc[4] + b1.x, 0.f);
    o1.y = fmaxf(acc[5] + b1.y, 0.f);
    o1.z = fmaxf(acc[6] + b1.z, 0.f);
    o1.w = fmaxf(acc[7] + b1.w, 0.f);

    float* dst = &out[(size_t)row * D_OUT + c];
    *reinterpret_cast<float4*>(dst)     = o0;
    *reinterpret_cast<float4*>(dst + 4) = o1;
}

// ---------------------------------------------------------------------------
// Launch:
//   side : cvt W -> monolithic GEMM (ev_g)
//   main : CSR build ; wait ev_g ; monolithic SpMM
// ---------------------------------------------------------------------------
static cudaStream_t g_side = nullptr;
static cudaEvent_t  g_fork = nullptr;
static cudaEvent_t  g_evg  = nullptr;

extern "C" void kernel_launch(void* const* d_in, const int* in_sizes, int n_in,
                              void* d_out, int out_size)
{
    const float* x         = (const float*)d_in[0];
    const int*   edge_row  = (const int*)  d_in[1];
    const int*   edge_col  = (const int*)  d_in[2];
    const float* edge_vals = (const float*)d_in[3];
    const float* weight    = (const float*)d_in[4];
    const float* bias      = (const float*)d_in[5];
    float* out = (float*)d_out;

    if (g_side == nullptr) {
        cudaStreamCreateWithFlags(&g_side, cudaStreamNonBlocking);
        cudaEventCreateWithFlags(&g_fork, cudaEventDisableTiming);
        cudaEventCreateWithFlags(&g_evg,  cudaEventDisableTiming);
    }

    // Fork side stream
    cudaEventRecord(g_fork, 0);
    cudaStreamWaitEvent(g_side, g_fork, 0);

    // Side: W conversion + monolithic GEMM (x converted in-kernel)
    {
        const size_t nw4 = (size_t)D_IN * D_OUT / 4;
        convert_w_kernel<<<(int)((nw4 + 255) / 256), 256, 0, g_side>>>(weight);
        dim3 ggrid(PAD_NODES / BLK_M, D_OUT / BLK_N);
        wmma_gemm_kernel<<<ggrid, 256, 0, g_side>>>(x);
        cudaEventRecord(g_evg, g_side);
    }

    // Main: CSR build (overlaps GEMM)
    zero_counts_kernel<<<(N_NODES + 255) / 256, 256>>>();
    count_kernel<<<(N_EDGES / 4 + 255) / 256, 256>>>(edge_row);
    scan_kernel<<<1, 1024>>>();
    fill_kernel<<<(N_EDGES / 4 + 255) / 256, 256>>>(edge_row, edge_col, edge_vals);

    // Main: SpMM after GEMM
    cudaStreamWaitEvent(0, g_evg, 0);
    const int spmm_blocks = (N_NODES * 32 + 255) / 256;
    spmm_kernel<<<spmm_blocks, 256>>>(bias, out);
}

// round 12
// speedup vs baseline: 1.9363x; 1.0435x over previous
#include <cuda_runtime.h>
#include <cuda_fp16.h>
#include <mma.h>
#include <cstdint>

using namespace nvcuda;

#define N_NODES   50000
#define PAD_NODES 50048        // multiple of 128 (GEMM M-tile)
#define N_EDGES   800000
#define D_IN      256
#define D_OUT     256

// ---------------- static device scratch (no allocations) -------------------
__device__ __align__(16) __half g_wh [(size_t)D_IN * D_OUT];       // W in fp16
__device__ __align__(16) __half g_xwh[(size_t)PAD_NODES * D_OUT];  // xw in fp16
__device__ __align__(16) int  g_deg[N_NODES];
__device__ __align__(16) int  g_fill[N_NODES];
__device__ __align__(16) int  g_rowptr[N_NODES + 1];
__device__ __align__(16) unsigned int g_epk[N_EDGES];   // {val_fp16 : col_u16}

// ---------------------------------------------------------------------------
// W fp32 -> fp16
// ---------------------------------------------------------------------------
__global__ __launch_bounds__(256)
void convert_w_kernel(const float* __restrict__ W)
{
    const size_t idx = (size_t)blockIdx.x * blockDim.x + threadIdx.x;
    const size_t i4  = idx * 4;
    if (i4 >= (size_t)D_IN * D_OUT) return;
    const float4 v = *reinterpret_cast<const float4*>(&W[i4]);
    const __half2 h01 = __floats2half2_rn(v.x, v.y);
    const __half2 h23 = __floats2half2_rn(v.z, v.w);
    uint2 u;
    u.x = *reinterpret_cast<const unsigned int*>(&h01);
    u.y = *reinterpret_cast<const unsigned int*>(&h23);
    *reinterpret_cast<uint2*>(&g_wh[i4]) = u;
}

// ---------------------------------------------------------------------------
// Monolithic HMMA GEMM: xwh = (half)(x @ W) — unchanged (R9/R10).
// ---------------------------------------------------------------------------
#define BLK_M 128
#define BLK_N 128
#define BLK_K 32
#define A_LD  (BLK_K + 8)
#define B_LD  (BLK_N + 8)

__global__ __launch_bounds__(256)
void wmma_gemm_kernel(const float* __restrict__ x)
{
    __shared__ __half As[2][BLK_M * A_LD];
    __shared__ __half Bs[2][BLK_K * B_LD];
    __shared__ float  ebuf[8][16 * 16];

    const int t    = threadIdx.x;
    const int warp = t >> 5;
    const int lane = t & 31;
    const int wm   = warp & 3;
    const int wn   = warp >> 2;
    const int row0 = blockIdx.x * BLK_M;
    const int col0 = blockIdx.y * BLK_N;

    wmma::fragment<wmma::accumulator, 16, 16, 16, float> acc[2][4];
    #pragma unroll
    for (int i = 0; i < 2; i++)
        #pragma unroll
        for (int j = 0; j < 4; j++)
            wmma::fill_fragment(acc[i][j], 0.0f);

    const int a_row = t >> 1;
    const int a_c16 = (t & 1) * 16;
    const int gm_a  = row0 + a_row;
    const bool a_ok = (gm_a < N_NODES);
    const float* a_ptr = x + (size_t)gm_a * D_IN + a_c16;

    auto load_a_g = [&](int k0, float4* r) {
        #pragma unroll
        for (int q = 0; q < 4; q++)
            r[q] = a_ok ? *reinterpret_cast<const float4*>(a_ptr + k0 + q * 4)
                        : make_float4(0.f, 0.f, 0.f, 0.f);
    };
    auto load_b_g = [&](int k0, uint4* r) {
        #pragma unroll
        for (int q = 0; q < 2; q++) {
            const int idx = t + q * 256;
            const int row = idx >> 4;
            const int c8  = (idx & 15) * 8;
            r[q] = *reinterpret_cast<const uint4*>(
                &g_wh[(size_t)(k0 + row) * D_OUT + col0 + c8]);
        }
    };
    auto store_a_s = [&](int buf, const float4* r) {
        union { __half h[16]; uint4 u[2]; } pk;
        #pragma unroll
        for (int q = 0; q < 4; q++) {
            const __half2 h01 = __floats2half2_rn(r[q].x, r[q].y);
            const __half2 h23 = __floats2half2_rn(r[q].z, r[q].w);
            pk.h[q * 4 + 0] = __low2half(h01);
            pk.h[q * 4 + 1] = __high2half(h01);
            pk.h[q * 4 + 2] = __low2half(h23);
            pk.h[q * 4 + 3] = __high2half(h23);
        }
        uint4* dst = reinterpret_cast<uint4*>(&As[buf][a_row * A_LD + a_c16]);
        dst[0] = pk.u[0];
        dst[1] = pk.u[1];
    };
    auto store_b_s = [&](int buf, const uint4* r) {
        #pragma unroll
        for (int q = 0; q < 2; q++) {
            const int idx = t + q * 256;
            const int row = idx >> 4;
            const int c8  = (idx & 15) * 8;
            *reinterpret_cast<uint4*>(&Bs[buf][row * B_LD + c8]) = r[q];
        }
    };

    float4 ra[4];
    uint4  rb[2];
    load_a_g(0, ra);
    load_b_g(0, rb);
    store_a_s(0, ra);
    store_b_s(0, rb);
    __syncthreads();

    const int NSTEP = D_IN / BLK_K;
    int buf = 0;

    for (int s = 0; s < NSTEP; s++) {
        if (s + 1 < NSTEP) {
            load_a_g((s + 1) * BLK_K, ra);
            load_b_g((s + 1) * BLK_K, rb);
        }

        #pragma unroll
        for (int kk = 0; kk < 2; kk++) {
            wmma::fragment<wmma::matrix_a, 16, 16, 16, __half, wmma::row_major> a0, a1;
            wmma::load_matrix_sync(a0, &As[buf][(wm * 32 +  0) * A_LD + kk * 16], A_LD);
            wmma::load_matrix_sync(a1, &As[buf][(wm * 32 + 16) * A_LD + kk * 16], A_LD);
            #pragma unroll
            for (int j = 0; j < 4; j++) {
                wmma::fragment<wmma::matrix_b, 16, 16, 16, __half, wmma::row_major> b;
                wmma::load_matrix_sync(b, &Bs[buf][(kk * 16) * B_LD + wn * 64 + j * 16], B_LD);
                wmma::mma_sync(acc[0][j], a0, b, acc[0][j]);
                wmma::mma_sync(acc[1][j], a1, b, acc[1][j]);
            }
        }

        if (s + 1 < NSTEP) {
            const int nb = buf ^ 1;
            store_a_s(nb, ra);
            store_b_s(nb, rb);
            __syncthreads();
            buf = nb;
        }
    }

    const int r  = lane >> 1;
    const int cc = (lane & 1) * 8;
    const int c0 = col0 + wn * 64;

    #pragma unroll
    for (int i = 0; i < 2; i++) {
        #pragma unroll
        for (int j = 0; j < 4; j++) {
            wmma::store_matrix_sync(ebuf[warp], acc[i][j], 16, wmma::mem_row_major);
            __syncwarp();
            const int grow = row0 + wm * 32 + i * 16 + r;
            if (grow < N_NODES) {
                union { __half h[8]; uint4 u; } pk;
                #pragma unroll
                for (int q = 0; q < 8; q++)
                    pk.h[q] = __float2half(ebuf[warp][r * 16 + cc + q]);
                *reinterpret_cast<uint4*>(&g_xwh[(size_t)grow * D_OUT + c0 + j * 16 + cc]) = pk.u;
            }
            __syncwarp();
        }
    }
}

// ---------------------------------------------------------------------------
// CSR construction
// ---------------------------------------------------------------------------
__global__ __launch_bounds__(256)
void count_kernel(const int* __restrict__ edge_row)
{
    const int e4 = (blockIdx.x * blockDim.x + threadIdx.x) * 4;
    if (e4 + 3 < N_EDGES) {
        const int4 r = *reinterpret_cast<const int4*>(&edge_row[e4]);
        atomicAdd(&g_deg[r.x], 1);
        atomicAdd(&g_deg[r.y], 1);
        atomicAdd(&g_deg[r.z], 1);
        atomicAdd(&g_deg[r.w], 1);
    } else {
        for (int e = e4; e < N_EDGES; e++)
            atomicAdd(&g_deg[edge_row[e]], 1);
    }
}

// Single-block exclusive scan, vectorized loads (CHUNK=52, int4).
__global__ __launch_bounds__(1024)
void scan_kernel()
{
    __shared__ int partial[1024];
    const int t = threadIdx.x;
    const int CHUNK = 52;                       // 1024*52 >= 50000, %4 == 0
    const int base = t * CHUNK;

    int s = 0;
    #pragma unroll
    for (int i = 0; i < CHUNK; i += 4) {
        const int idx = base + i;
        if (idx + 3 < N_NODES) {
            const int4 d = *reinterpret_cast<const int4*>(&g_deg[idx]);
            s += d.x + d.y + d.z + d.w;
        } else {
            for (int q = 0; q < 4; q++)
                if (idx + q < N_NODES) s += g_deg[idx + q];
        }
    }
    partial[t] = s;
    __syncthreads();

    for (int off = 1; off < 1024; off <<= 1) {
        int v = (t >= off) ? partial[t - off] : 0;
        __syncthreads();
        partial[t] += v;
        __syncthreads();
    }

    int run = (t == 0) ? 0 : partial[t - 1];
    for (int i = 0; i < CHUNK; i++) {
        const int idx = base + i;
        if (idx < N_NODES) { g_rowptr[idx] = run; run += g_deg[idx]; }
    }
    if (t == 1023) g_rowptr[N_NODES] = partial[1023];
}

__device__ __forceinline__ unsigned int pack_edge(int col, float v)
{
    const unsigned short hv = __half_as_ushort(__float2half_rn(v));
    return (unsigned int)col | ((unsigned int)hv << 16);
}

__global__ __launch_bounds__(256)
void fill_kernel(const int*   __restrict__ edge_row,
                 const int*   __restrict__ edge_col,
                 const float* __restrict__ edge_vals)
{
    const int e4 = (blockIdx.x * blockDim.x + threadIdx.x) * 4;
    if (e4 + 3 < N_EDGES) {
        const int4   r = *reinterpret_cast<const int4*>(&edge_row[e4]);
        const int4   c = *reinterpret_cast<const int4*>(&edge_col[e4]);
        const float4 v = *reinterpret_cast<const float4*>(&edge_vals[e4]);
        int p;
        p = g_rowptr[r.x] + atomicAdd(&g_fill[r.x], 1);
        g_epk[p] = pack_edge(c.x, v.x);
        p = g_rowptr[r.y] + atomicAdd(&g_fill[r.y], 1);
        g_epk[p] = pack_edge(c.y, v.y);
        p = g_rowptr[r.z] + atomicAdd(&g_fill[r.z], 1);
        g_epk[p] = pack_edge(c.z, v.z);
        p = g_rowptr[r.w] + atomicAdd(&g_fill[r.w], 1);
        g_epk[p] = pack_edge(c.w, v.w);
    } else {
        for (int e = e4; e < N_EDGES; e++) {
            const int rr = edge_row[e];
            const int p = g_rowptr[rr] + atomicAdd(&g_fill[rr], 1);
            g_epk[p] = pack_edge(edge_col[e], edge_vals[e]);
        }
    }
}

// ---------------------------------------------------------------------------
// Monolithic SpMM: out = relu(A @ xwh + bias)
// One warp per row; lane owns 8 halves (uint4 = 512B warp gather/edge);
// packed 4B edges: one coalesced fetch + ONE shfl per edge; 8-edge unroll.
// Streaming stores for out.
// ---------------------------------------------------------------------------
__device__ __forceinline__ void fma_half8(float* acc, float v, uint4 m)
{
    const __half2* h = reinterpret_cast<const __half2*>(&m);
    #pragma unroll
    for (int q = 0; q < 4; q++) {
        const float2 f = __half22float2(h[q]);
        acc[q * 2 + 0] = fmaf(v, f.x, acc[q * 2 + 0]);
        acc[q * 2 + 1] = fmaf(v, f.y, acc[q * 2 + 1]);
    }
}

__device__ __forceinline__ float epk_val(unsigned int pk)
{
    return __half2float(__ushort_as_half((unsigned short)(pk >> 16)));
}

__global__ __launch_bounds__(256)
void spmm_kernel(const float* __restrict__ bias,
                 float*       __restrict__ out)
{
    const int row  = (blockIdx.x * blockDim.x + threadIdx.x) >> 5;
    const int lane = threadIdx.x & 31;
    if (row >= N_NODES) return;

    const int s = g_rowptr[row];
    const int e = g_rowptr[row + 1];
    const int c = lane * 8;

    float acc[8];
    #pragma unroll
    for (int q = 0; q < 8; q++) acc[q] = 0.f;

    int base = s;
    while (base < e) {
        const int navail = min(32, e - base);

        unsigned int pk_lane = 0;
        if (lane < navail) pk_lane = __ldg(&g_epk[base + lane]);

        int j = 0;
        for (; j + 7 < navail; j += 8) {
            unsigned int pk[8];
            uint4 m[8];
            #pragma unroll
            for (int q = 0; q < 8; q++)
                pk[q] = __shfl_sync(0xffffffffu, pk_lane, j + q);
            #pragma unroll
            for (int q = 0; q < 8; q++)
                m[q] = __ldg(reinterpret_cast<const uint4*>(
                    &g_xwh[(size_t)(pk[q] & 0xFFFFu) * D_OUT + c]));
            #pragma unroll
            for (int q = 0; q < 8; q++)
                fma_half8(acc, epk_val(pk[q]), m[q]);
        }
        if (j + 3 < navail) {
            unsigned int pk[4];
            uint4 m[4];
            #pragma unroll
            for (int q = 0; q < 4; q++)
                pk[q] = __shfl_sync(0xffffffffu, pk_lane, j + q);
            #pragma unroll
            for (int q = 0; q < 4; q++)
                m[q] = __ldg(reinterpret_cast<const uint4*>(
                    &g_xwh[(size_t)(pk[q] & 0xFFFFu) * D_OUT + c]));
            #pragma unroll
            for (int q = 0; q < 4; q++)
                fma_half8(acc, epk_val(pk[q]), m[q]);
            j += 4;
        }
        for (; j < navail; j++) {
            const unsigned int pk = __shfl_sync(0xffffffffu, pk_lane, j);
            const uint4 m = __ldg(reinterpret_cast<const uint4*>(
                &g_xwh[(size_t)(pk & 0xFFFFu) * D_OUT + c]));
            fma_half8(acc, epk_val(pk), m);
        }
        base += navail;
    }

    const float4 b0 = *reinterpret_cast<const float4*>(&bias[c]);
    const float4 b1 = *reinterpret_cast<const float4*>(&bias[c + 4]);
    float4 o0, o1;
    o0.x = fmaxf(acc[0] + b0.x, 0.f);
    o0.y = fmaxf(acc[1] + b0.y, 0.f);
    o0.z = fmaxf(acc[2] + b0.z, 0.f);
    o0.w = fmaxf(acc[3] + b0.w, 0.f);
    o1.x = fmaxf(acc[4] + b1.x, 0.f);
    o1.y = fmaxf(acc[5] + b1.y, 0.f);
    o1.z = fmaxf(acc[6] + b1.z, 0.f);
    o1.w = fmaxf(acc[7] + b1.w, 0.f);

    float* dst = &out[(size_t)row * D_OUT + c];
    __stcs(reinterpret_cast<float4*>(dst),     o0);
    __stcs(reinterpret_cast<float4*>(dst + 4), o1);
}

// ---------------------------------------------------------------------------
// Launch:
//   side : cvt W -> monolithic GEMM (ev_g)
//   main : memset deg/fill ; count ; scan ; fill ; wait ev_g ; SpMM
// ---------------------------------------------------------------------------
static cudaStream_t g_side = nullptr;
static cudaEvent_t  g_fork = nullptr;
static cudaEvent_t  g_evg  = nullptr;
static void* g_deg_ptr  = nullptr;
static void* g_fill_ptr = nullptr;

extern "C" void kernel_launch(void* const* d_in, const int* in_sizes, int n_in,
                              void* d_out, int out_size)
{
    const float* x         = (const float*)d_in[0];
    const int*   edge_row  = (const int*)  d_in[1];
    const int*   edge_col  = (const int*)  d_in[2];
    const float* edge_vals = (const float*)d_in[3];
    const float* weight    = (const float*)d_in[4];
    const float* bias      = (const float*)d_in[5];
    float* out = (float*)d_out;

    if (g_side == nullptr) {
        cudaStreamCreateWithFlags(&g_side, cudaStreamNonBlocking);
        cudaEventCreateWithFlags(&g_fork, cudaEventDisableTiming);
        cudaEventCreateWithFlags(&g_evg,  cudaEventDisableTiming);
        cudaGetSymbolAddress(&g_deg_ptr,  g_deg);
        cudaGetSymbolAddress(&g_fill_ptr, g_fill);
    }

    // Fork side stream
    cudaEventRecord(g_fork, 0);
    cudaStreamWaitEvent(g_side, g_fork, 0);

    // Side: W conversion + monolithic GEMM (x converted in-kernel)
    {
        const size_t nw4 = (size_t)D_IN * D_OUT / 4;
        convert_w_kernel<<<(int)((nw4 + 255) / 256), 256, 0, g_side>>>(weight);
        dim3 ggrid(PAD_NODES / BLK_M, D_OUT / BLK_N);
        wmma_gemm_kernel<<<ggrid, 256, 0, g_side>>>(x);
        cudaEventRecord(g_evg, g_side);
    }

    // Main: CSR build (overlaps GEMM)
    cudaMemsetAsync(g_deg_ptr,  0, N_NODES * sizeof(int), 0);
    cudaMemsetAsync(g_fill_ptr, 0, N_NODES * sizeof(int), 0);
    count_kernel<<<(N_EDGES / 4 + 255) / 256, 256>>>(edge_row);
    scan_kernel<<<1, 1024>>>();
    fill_kernel<<<(N_EDGES / 4 + 255) / 256, 256>>>(edge_row, edge_col, edge_vals);

    // Main: SpMM after GEMM
    cudaStreamWaitEvent(0, g_evg, 0);
    const int spmm_blocks = (N_NODES * 32 + 255) / 256;
    spmm_kernel<<<spmm_blocks, 256>>>(bias, out);
}

// round 13
// speedup vs baseline: 2.6494x; 1.3683x over previous
#include <cuda_runtime.h>
#include <cuda_fp16.h>
#include <mma.h>
#include <cstdint>

using namespace nvcuda;

#define N_NODES   50000
#define PAD_NODES 50048        // multiple of 128 (GEMM M-tile)
#define N_EDGES   800000
#define D_IN      256
#define D_OUT     256

#define SCAN_BLKS 196          // 196*256 = 50176 >= N_NODES

// ---------------- static device scratch (no allocations) -------------------
__device__ __align__(16) __half g_wh [(size_t)D_IN * D_OUT];       // W in fp16
__device__ __align__(16) __half g_xwh[(size_t)PAD_NODES * D_OUT];  // xw in fp16
__device__ __align__(16) int  g_deg[N_NODES];
__device__ __align__(16) int  g_fill[N_NODES];
__device__ __align__(16) int  g_rowptr[N_NODES + 1];
__device__ __align__(16) int  g_bsum[256];
__device__ __align__(16) int  g_boff[256];
__device__ __align__(16) unsigned int g_epk[N_EDGES];   // {val_fp16 : col_u16}

// ---------------------------------------------------------------------------
// W fp32 -> fp16
// ---------------------------------------------------------------------------
__global__ __launch_bounds__(256)
void convert_w_kernel(const float* __restrict__ W)
{
    const size_t idx = (size_t)blockIdx.x * blockDim.x + threadIdx.x;
    const size_t i4  = idx * 4;
    if (i4 >= (size_t)D_IN * D_OUT) return;
    const float4 v = *reinterpret_cast<const float4*>(&W[i4]);
    const __half2 h01 = __floats2half2_rn(v.x, v.y);
    const __half2 h23 = __floats2half2_rn(v.z, v.w);
    uint2 u;
    u.x = *reinterpret_cast<const unsigned int*>(&h01);
    u.y = *reinterpret_cast<const unsigned int*>(&h23);
    *reinterpret_cast<uint2*>(&g_wh[i4]) = u;
}

// ---------------------------------------------------------------------------
// Monolithic HMMA GEMM: xwh = (half)(x @ W) — unchanged.
// ---------------------------------------------------------------------------
#define BLK_M 128
#define BLK_N 128
#define BLK_K 32
#define A_LD  (BLK_K + 8)
#define B_LD  (BLK_N + 8)

__global__ __launch_bounds__(256)
void wmma_gemm_kernel(const float* __restrict__ x)
{
    __shared__ __half As[2][BLK_M * A_LD];
    __shared__ __half Bs[2][BLK_K * B_LD];
    __shared__ float  ebuf[8][16 * 16];

    const int t    = threadIdx.x;
    const int warp = t >> 5;
    const int lane = t & 31;
    const int wm   = warp & 3;
    const int wn   = warp >> 2;
    const int row0 = blockIdx.x * BLK_M;
    const int col0 = blockIdx.y * BLK_N;

    wmma::fragment<wmma::accumulator, 16, 16, 16, float> acc[2][4];
    #pragma unroll
    for (int i = 0; i < 2; i++)
        #pragma unroll
        for (int j = 0; j < 4; j++)
            wmma::fill_fragment(acc[i][j], 0.0f);

    const int a_row = t >> 1;
    const int a_c16 = (t & 1) * 16;
    const int gm_a  = row0 + a_row;
    const bool a_ok = (gm_a < N_NODES);
    const float* a_ptr = x + (size_t)gm_a * D_IN + a_c16;

    auto load_a_g = [&](int k0, float4* r) {
        #pragma unroll
        for (int q = 0; q < 4; q++)
            r[q] = a_ok ? *reinterpret_cast<const float4*>(a_ptr + k0 + q * 4)
                        : make_float4(0.f, 0.f, 0.f, 0.f);
    };
    auto load_b_g = [&](int k0, uint4* r) {
        #pragma unroll
        for (int q = 0; q < 2; q++) {
            const int idx = t + q * 256;
            const int row = idx >> 4;
            const int c8  = (idx & 15) * 8;
            r[q] = *reinterpret_cast<const uint4*>(
                &g_wh[(size_t)(k0 + row) * D_OUT + col0 + c8]);
        }
    };
    auto store_a_s = [&](int buf, const float4* r) {
        union { __half h[16]; uint4 u[2]; } pk;
        #pragma unroll
        for (int q = 0; q < 4; q++) {
            const __half2 h01 = __floats2half2_rn(r[q].x, r[q].y);
            const __half2 h23 = __floats2half2_rn(r[q].z, r[q].w);
            pk.h[q * 4 + 0] = __low2half(h01);
            pk.h[q * 4 + 1] = __high2half(h01);
            pk.h[q * 4 + 2] = __low2half(h23);
            pk.h[q * 4 + 3] = __high2half(h23);
        }
        uint4* dst = reinterpret_cast<uint4*>(&As[buf][a_row * A_LD + a_c16]);
        dst[0] = pk.u[0];
        dst[1] = pk.u[1];
    };
    auto store_b_s = [&](int buf, const uint4* r) {
        #pragma unroll
        for (int q = 0; q < 2; q++) {
            const int idx = t + q * 256;
            const int row = idx >> 4;
            const int c8  = (idx & 15) * 8;
            *reinterpret_cast<uint4*>(&Bs[buf][row * B_LD + c8]) = r[q];
        }
    };

    float4 ra[4];
    uint4  rb[2];
    load_a_g(0, ra);
    load_b_g(0, rb);
    store_a_s(0, ra);
    store_b_s(0, rb);
    __syncthreads();

    const int NSTEP = D_IN / BLK_K;
    int buf = 0;

    for (int s = 0; s < NSTEP; s++) {
        if (s + 1 < NSTEP) {
            load_a_g((s + 1) * BLK_K, ra);
            load_b_g((s + 1) * BLK_K, rb);
        }

        #pragma unroll
        for (int kk = 0; kk < 2; kk++) {
            wmma::fragment<wmma::matrix_a, 16, 16, 16, __half, wmma::row_major> a0, a1;
            wmma::load_matrix_sync(a0, &As[buf][(wm * 32 +  0) * A_LD + kk * 16], A_LD);
            wmma::load_matrix_sync(a1, &As[buf][(wm * 32 + 16) * A_LD + kk * 16], A_LD);
            #pragma unroll
            for (int j = 0; j < 4; j++) {
                wmma::fragment<wmma::matrix_b, 16, 16, 16, __half, wmma::row_major> b;
                wmma::load_matrix_sync(b, &Bs[buf][(kk * 16) * B_LD + wn * 64 + j * 16], B_LD);
                wmma::mma_sync(acc[0][j], a0, b, acc[0][j]);
                wmma::mma_sync(acc[1][j], a1, b, acc[1][j]);
            }
        }

        if (s + 1 < NSTEP) {
            const int nb = buf ^ 1;
            store_a_s(nb, ra);
            store_b_s(nb, rb);
            __syncthreads();
            buf = nb;
        }
    }

    const int r  = lane >> 1;
    const int cc = (lane & 1) * 8;
    const int c0 = col0 + wn * 64;

    #pragma unroll
    for (int i = 0; i < 2; i++) {
        #pragma unroll
        for (int j = 0; j < 4; j++) {
            wmma::store_matrix_sync(ebuf[warp], acc[i][j], 16, wmma::mem_row_major);
            __syncwarp();
            const int grow = row0 + wm * 32 + i * 16 + r;
            if (grow < N_NODES) {
                union { __half h[8]; uint4 u; } pk;
                #pragma unroll
                for (int q = 0; q < 8; q++)
                    pk.h[q] = __float2half(ebuf[warp][r * 16 + cc + q]);
                *reinterpret_cast<uint4*>(&g_xwh[(size_t)grow * D_OUT + c0 + j * 16 + cc]) = pk.u;
            }
            __syncwarp();
        }
    }
}

// ---------------------------------------------------------------------------
// CSR construction — 3-phase parallel scan replaces the single-block scan.
// ---------------------------------------------------------------------------
__global__ __launch_bounds__(256)
void count_kernel(const int* __restrict__ edge_row)
{
    const int e4 = (blockIdx.x * blockDim.x + threadIdx.x) * 4;
    if (e4 + 3 < N_EDGES) {
        const int4 r = *reinterpret_cast<const int4*>(&edge_row[e4]);
        atomicAdd(&g_deg[r.x], 1);
        atomicAdd(&g_deg[r.y], 1);
        atomicAdd(&g_deg[r.z], 1);
        atomicAdd(&g_deg[r.w], 1);
    } else {
        for (int e = e4; e < N_EDGES; e++)
            atomicAdd(&g_deg[edge_row[e]], 1);
    }
}

// Phase 1: per-block (256-wide) scan; writes local-exclusive prefix + block sum.
__global__ __launch_bounds__(256)
void scan_phase1()
{
    __shared__ int sh[256];
    const int t = threadIdx.x;
    const int i = blockIdx.x * 256 + t;
    const int v = (i < N_NODES) ? g_deg[i] : 0;

    sh[t] = v;
    __syncthreads();
    #pragma unroll
    for (int off = 1; off < 256; off <<= 1) {
        const int u = (t >= off) ? sh[t - off] : 0;
        __syncthreads();
        sh[t] += u;
        __syncthreads();
    }

    if (i < N_NODES) g_rowptr[i] = sh[t] - v;       // local exclusive
    if (t == 255) g_bsum[blockIdx.x] = sh[255];     // block total
}

// Phase 2: one block scans the SCAN_BLKS block sums (exclusive).
__global__ __launch_bounds__(256)
void scan_phase2()
{
    __shared__ int sh[256];
    const int t = threadIdx.x;
    const int v = (t < SCAN_BLKS) ? g_bsum[t] : 0;

    sh[t] = v;
    __syncthreads();
    #pragma unroll
    for (int off = 1; off < 256; off <<= 1) {
        const int u = (t >= off) ? sh[t - off] : 0;
        __syncthreads();
        sh[t] += u;
        __syncthreads();
    }

    g_boff[t] = sh[t] - v;                           // exclusive block offset
}

// Phase 3: add block offsets; rowptr[N] is the known edge total.
__global__ __launch_bounds__(256)
void scan_phase3()
{
    const int i = blockIdx.x * 256 + threadIdx.x;
    if (i < N_NODES) g_rowptr[i] += g_boff[blockIdx.x];
    if (i == 0) g_rowptr[N_NODES] = N_EDGES;
}

__device__ __forceinline__ unsigned int pack_edge(int col, float v)
{
    const unsigned short hv = __half_as_ushort(__float2half_rn(v));
    return (unsigned int)col | ((unsigned int)hv << 16);
}

__global__ __launch_bounds__(256)
void fill_kernel(const int*   __restrict__ edge_row,
                 const int*   __restrict__ edge_col,
                 const float* __restrict__ edge_vals)
{
    const int e4 = (blockIdx.x * blockDim.x + threadIdx.x) * 4;
    if (e4 + 3 < N_EDGES) {
        const int4   r = *reinterpret_cast<const int4*>(&edge_row[e4]);
        const int4   c = *reinterpret_cast<const int4*>(&edge_col[e4]);
        const float4 v = *reinterpret_cast<const float4*>(&edge_vals[e4]);
        int p;
        p = g_rowptr[r.x] + atomicAdd(&g_fill[r.x], 1);
        g_epk[p] = pack_edge(c.x, v.x);
        p = g_rowptr[r.y] + atomicAdd(&g_fill[r.y], 1);
        g_epk[p] = pack_edge(c.y, v.y);
        p = g_rowptr[r.z] + atomicAdd(&g_fill[r.z], 1);
        g_epk[p] = pack_edge(c.z, v.z);
        p = g_rowptr[r.w] + atomicAdd(&g_fill[r.w], 1);
        g_epk[p] = pack_edge(c.w, v.w);
    } else {
        for (int e = e4; e < N_EDGES; e++) {
            const int rr = edge_row[e];
            const int p = g_rowptr[rr] + atomicAdd(&g_fill[rr], 1);
            g_epk[p] = pack_edge(edge_col[e], edge_vals[e]);
        }
    }
}

// ---------------------------------------------------------------------------
// Monolithic SpMM: out = relu(A @ xwh + bias) — unchanged (R11).
// ---------------------------------------------------------------------------
__device__ __forceinline__ void fma_half8(float* acc, float v, uint4 m)
{
    const __half2* h = reinterpret_cast<const __half2*>(&m);
    #pragma unroll
    for (int q = 0; q < 4; q++) {
        const float2 f = __half22float2(h[q]);
        acc[q * 2 + 0] = fmaf(v, f.x, acc[q * 2 + 0]);
        acc[q * 2 + 1] = fmaf(v, f.y, acc[q * 2 + 1]);
    }
}

__device__ __forceinline__ float epk_val(unsigned int pk)
{
    return __half2float(__ushort_as_half((unsigned short)(pk >> 16)));
}

__global__ __launch_bounds__(256)
void spmm_kernel(const float* __restrict__ bias,
                 float*       __restrict__ out)
{
    const int row  = (blockIdx.x * blockDim.x + threadIdx.x) >> 5;
    const int lane = threadIdx.x & 31;
    if (row >= N_NODES) return;

    const int s = g_rowptr[row];
    const int e = g_rowptr[row + 1];
    const int c = lane * 8;

    float acc[8];
    #pragma unroll
    for (int q = 0; q < 8; q++) acc[q] = 0.f;

    int base = s;
    while (base < e) {
        const int navail = min(32, e - base);

        unsigned int pk_lane = 0;
        if (lane < navail) pk_lane = __ldg(&g_epk[base + lane]);

        int j = 0;
        for (; j + 7 < navail; j += 8) {
            unsigned int pk[8];
            uint4 m[8];
            #pragma unroll
            for (int q = 0; q < 8; q++)
                pk[q] = __shfl_sync(0xffffffffu, pk_lane, j + q);
            #pragma unroll
            for (int q = 0; q < 8; q++)
                m[q] = __ldg(reinterpret_cast<const uint4*>(
                    &g_xwh[(size_t)(pk[q] & 0xFFFFu) * D_OUT + c]));
            #pragma unroll
            for (int q = 0; q < 8; q++)
                fma_half8(acc, epk_val(pk[q]), m[q]);
        }
        if (j + 3 < navail) {
            unsigned int pk[4];
            uint4 m[4];
            #pragma unroll
            for (int q = 0; q < 4; q++)
                pk[q] = __shfl_sync(0xffffffffu, pk_lane, j + q);
            #pragma unroll
            for (int q = 0; q < 4; q++)
                m[q] = __ldg(reinterpret_cast<const uint4*>(
                    &g_xwh[(size_t)(pk[q] & 0xFFFFu) * D_OUT + c]));
            #pragma unroll
            for (int q = 0; q < 4; q++)
                fma_half8(acc, epk_val(pk[q]), m[q]);
            j += 4;
        }
        for (; j < navail; j++) {
            const unsigned int pk = __shfl_sync(0xffffffffu, pk_lane, j);
            const uint4 m = __ldg(reinterpret_cast<const uint4*>(
                &g_xwh[(size_t)(pk & 0xFFFFu) * D_OUT + c]));
            fma_half8(acc, epk_val(pk), m);
        }
        base += navail;
    }

    const float4 b0 = *reinterpret_cast<const float4*>(&bias[c]);
    const float4 b1 = *reinterpret_cast<const float4*>(&bias[c + 4]);
    float4 o0, o1;
    o0.x = fmaxf(acc[0] + b0.x, 0.f);
    o0.y = fmaxf(acc[1] + b0.y, 0.f);
    o0.z = fmaxf(acc[2] + b0.z, 0.f);
    o0.w = fmaxf(acc[3] + b0.w, 0.f);
    o1.x = fmaxf(acc[4] + b1.x, 0.f);
    o1.y = fmaxf(acc[5] + b1.y, 0.f);
    o1.z = fmaxf(acc[6] + b1.z, 0.f);
    o1.w = fmaxf(acc[7] + b1.w, 0.f);

    float* dst = &out[(size_t)row * D_OUT + c];
    __stcs(reinterpret_cast<float4*>(dst),     o0);
    __stcs(reinterpret_cast<float4*>(dst + 4), o1);
}

// ---------------------------------------------------------------------------
// Launch:
//   side : cvt W -> monolithic GEMM (ev_g)
//   main : memset deg/fill ; count ; scan x3 ; fill ; wait ev_g ; SpMM
// ---------------------------------------------------------------------------
static cudaStream_t g_side = nullptr;
static cudaEvent_t  g_fork = nullptr;
static cudaEvent_t  g_evg  = nullptr;
static void* g_deg_ptr  = nullptr;
static void* g_fill_ptr = nullptr;

extern "C" void kernel_launch(void* const* d_in, const int* in_sizes, int n_in,
                              void* d_out, int out_size)
{
    const float* x         = (const float*)d_in[0];
    const int*   edge_row  = (const int*)  d_in[1];
    const int*   edge_col  = (const int*)  d_in[2];
    const float* edge_vals = (const float*)d_in[3];
    const float* weight    = (const float*)d_in[4];
    const float* bias      = (const float*)d_in[5];
    float* out = (float*)d_out;

    if (g_side == nullptr) {
        cudaStreamCreateWithFlags(&g_side, cudaStreamNonBlocking);
        cudaEventCreateWithFlags(&g_fork, cudaEventDisableTiming);
        cudaEventCreateWithFlags(&g_evg,  cudaEventDisableTiming);
        cudaGetSymbolAddress(&g_deg_ptr,  g_deg);
        cudaGetSymbolAddress(&g_fill_ptr, g_fill);
    }

    // Fork side stream
    cudaEventRecord(g_fork, 0);
    cudaStreamWaitEvent(g_side, g_fork, 0);

    // Side: W conversion + monolithic GEMM (x converted in-kernel)
    {
        const size_t nw4 = (size_t)D_IN * D_OUT / 4;
        convert_w_kernel<<<(int)((nw4 + 255) / 256), 256, 0, g_side>>>(weight);
        dim3 ggrid(PAD_NODES / BLK_M, D_OUT / BLK_N);
        wmma_gemm_kernel<<<ggrid, 256, 0, g_side>>>(x);
        cudaEventRecord(g_evg, g_side);
    }

    // Main: CSR build (overlaps GEMM)
    cudaMemsetAsync(g_deg_ptr,  0, N_NODES * sizeof(int), 0);
    cudaMemsetAsync(g_fill_ptr, 0, N_NODES * sizeof(int), 0);
    count_kernel<<<(N_EDGES / 4 + 255) / 256, 256>>>(edge_row);
    scan_phase1<<<SCAN_BLKS, 256>>>();
    scan_phase2<<<1, 256>>>();
    scan_phase3<<<SCAN_BLKS, 256>>>();
    fill_kernel<<<(N_EDGES / 4 + 255) / 256, 256>>>(edge_row, edge_col, edge_vals);

    // Main: SpMM after GEMM
    cudaStreamWaitEvent(0, g_evg, 0);
    const int spmm_blocks = (N_NODES * 32 + 255) / 256;
    spmm_kernel<<<spmm_blocks, 256>>>(bias, out);
}